// round 14
// baseline (speedup 1.0000x reference)
#include <cuda_runtime.h>
#include <cuda_fp16.h>
#include <math.h>
#include <stdint.h>

#define BATCH 2
#define SEQ 2048
#define NTOK (BATCH*SEQ)
#define DMODEL 1024
#define DFF 2048
#define NHEADS 16
#define NKVHEADS 4
#define HD 64
#define KVDIM (NKVHEADS*HD)
#define QKVN (DMODEL+2*KVDIM)   // 1536
#define K3 (3*DMODEL)           // 3072 split-K
#define NEXP 8
#define TOPK 2
#define NSLOT (NTOK*TOPK)
#define NSLOT_PAD 9216

__device__ float  g_xn[NTOK*DMODEL];
__device__ __half g_xns[NTOK*K3];
__device__ __half g_xnt[NTOK*DMODEL];
__device__ float  g_qkv[NTOK*QKVN];
__device__ __half g_attns[NTOK*K3];
__device__ float  g_x1[NTOK*DMODEL];
__device__ __half g_Hh[NSLOT_PAD*DFF];
__device__ float  g_Y[NSLOT_PAD*DMODEL];
__device__ __half g_Wqkvs[QKVN*K3];
__device__ __half g_Wos[DMODEL*K3];
__device__ __half g_Wgt[NEXP*DFF*DMODEL];
__device__ __half g_Wut[NEXP*DFF*DMODEL];
__device__ __half g_Wdt[NEXP*DMODEL*DFF];
__device__ int    g_perm[NSLOT_PAD];
__device__ float  g_prob[NSLOT_PAD];
__device__ int    g_posOf[NTOK*TOPK];
__device__ int    g_topk_e[NTOK*TOPK];
__device__ float  g_topk_p[NTOK*TOPK];
__device__ float  g_probs_all[NTOK*NEXP];
__device__ int    g_cnt[NEXP];
__device__ int    g_off[NEXP+1];
__device__ int    g_cur[NEXP];
__device__ float  g_Psum[NEXP];

__device__ __forceinline__ void cp16(uint32_t dst, const void* src, uint32_t sz) {
    asm volatile("cp.async.cg.shared.global [%0], [%1], 16, %2;" :: "r"(dst), "l"(src), "r"(sz) : "memory");
}
__device__ __forceinline__ uint32_t smem_u32(const void* p) {
    uint32_t a;
    asm("{ .reg .u64 t; cvta.to.shared.u64 t, %1; cvt.u32.u64 %0, t; }" : "=r"(a) : "l"(p));
    return a;
}
__device__ __forceinline__ void mma16h(float* c, uint32_t a0, uint32_t a1, uint32_t a2,
                                       uint32_t a3, uint32_t b0, uint32_t b1) {
    asm volatile("mma.sync.aligned.m16n8k16.row.col.f32.f16.f16.f32 "
        "{%0,%1,%2,%3}, {%4,%5,%6,%7}, {%8,%9}, {%0,%1,%2,%3};"
        : "+f"(c[0]), "+f"(c[1]), "+f"(c[2]), "+f"(c[3])
        : "r"(a0), "r"(a1), "r"(a2), "r"(a3), "r"(b0), "r"(b1));
}
__device__ __forceinline__ float silu(float g) { return g / (1.f + __expf(-g)); }
__device__ __forceinline__ void split2(float x, float y, __half2& h, __half2& l) {
    __half hx = __float2half_rn(x), hy = __float2half_rn(y);
    h = __halves2half2(hx, hy);
    l = __floats2half2_rn(x - __half2float(hx), y - __half2float(hy));
}

__global__ void init_kernel() {
    int i = blockIdx.x*256 + threadIdx.x;
    if (i < NSLOT_PAD) g_perm[i] = -1;
    if (i < NEXP) { g_cnt[i] = 0; g_Psum[i] = 0.f; }
}

__global__ void cvth_kernel(const float4* __restrict__ src, __half2* __restrict__ dst, int n4) {
    int i = blockIdx.x*256 + threadIdx.x;
    if (i < n4) {
        float4 v = src[i];
        dst[2*i]   = __floats2half2_rn(v.x, v.y);
        dst[2*i+1] = __floats2half2_rn(v.z, v.w);
    }
}

__device__ __forceinline__ void cvtsplit_one(const float4* src, __half* dst, int K, int i) {
    int kq = K >> 2;
    int n = i / kq, c = (i - n*kq) * 4;
    float4 v = src[i];
    __half2 h0, l0, h1, l1;
    split2(v.x, v.y, h0, l0);
    split2(v.z, v.w, h1, l1);
    __half2* d = (__half2*)(dst + (size_t)n*3*K);
    d[c/2] = h0;         d[c/2+1] = h1;
    d[(K+c)/2] = h0;     d[(K+c)/2+1] = h1;
    d[(2*K+c)/2] = l0;   d[(2*K+c)/2+1] = l1;
}

__global__ void cvtsplit_kernel(const float4* __restrict__ src, __half* __restrict__ dst,
                                int K, int n4) {
    int i = blockIdx.x*256 + threadIdx.x;
    if (i < n4) cvtsplit_one(src, dst, K, i);
}

#define NWQ (DMODEL*DMODEL/4)
#define NWK (KVDIM*DMODEL/4)
__global__ void cvtsplit3_kernel(const float4* __restrict__ wq, const float4* __restrict__ wk,
                                 const float4* __restrict__ wv, __half* __restrict__ dst) {
    int i = blockIdx.x*256 + threadIdx.x;
    if (i < NWQ) {
        cvtsplit_one(wq, dst, DMODEL, i);
    } else if (i < NWQ + NWK) {
        cvtsplit_one(wk, dst + (size_t)DMODEL*K3, DMODEL, i - NWQ);
    } else if (i < NWQ + 2*NWK) {
        cvtsplit_one(wv, dst + (size_t)(DMODEL+KVDIM)*K3, DMODEL, i - NWQ - NWK);
    }
}

__global__ void rmsnorm_kernel(const float* __restrict__ X, const float* __restrict__ W,
                               float* __restrict__ Y, __half* __restrict__ Yt,
                               __half* __restrict__ Ys) {
    int t = blockIdx.x;
    int tid = threadIdx.x;
    float4 xv = ((const float4*)(X + (long long)t*DMODEL))[tid];
    float ss = xv.x*xv.x + xv.y*xv.y + xv.z*xv.z + xv.w*xv.w;
    #pragma unroll
    for (int off=16; off; off>>=1) ss += __shfl_xor_sync(0xffffffffu, ss, off);
    __shared__ float red[8];
    if ((tid & 31) == 0) red[tid>>5] = ss;
    __syncthreads();
    if (tid < 8) {
        float v = red[tid];
        #pragma unroll
        for (int off=4; off; off>>=1) v += __shfl_xor_sync(0xffu, v, off);
        if (tid == 0) red[0] = v;
    }
    __syncthreads();
    float r = rsqrtf(red[0]/(float)DMODEL + 1e-6f);
    float4 wv = ((const float4*)W)[tid];
    float4 o = make_float4(xv.x*r*wv.x, xv.y*r*wv.y, xv.z*r*wv.z, xv.w*r*wv.w);
    if (Y) ((float4*)(Y + (long long)t*DMODEL))[tid] = o;
    if (Yt) {
        __half2* yh = (__half2*)(Yt + (long long)t*DMODEL);
        yh[2*tid]   = __floats2half2_rn(o.x, o.y);
        yh[2*tid+1] = __floats2half2_rn(o.z, o.w);
    }
    if (Ys) {
        int c = 4*tid;
        __half2 h0,l0,h1,l1;
        split2(o.x, o.y, h0, l0);
        split2(o.z, o.w, h1, l1);
        __half2* d = (__half2*)(Ys + (size_t)t*K3);
        d[c/2] = h0;              d[c/2+1] = h1;
        d[(DMODEL+c)/2] = l0;     d[(DMODEL+c)/2+1] = l1;
        d[(2*DMODEL+c)/2] = h0;   d[(2*DMODEL+c)/2+1] = h1;
    }
}

__device__ __forceinline__ void rope_pair(int row, int col, float& c0, float& c1) {
    int s = row & (SEQ-1);
    int elem = col & 63;
    float f = (float)(elem & 31);
    float freq = powf(10000.f, -f/32.f);
    float ang = (float)s * freq;
    float cc = cosf(ang), sn = sinf(ang);
    float x1 = c0, x2 = c1;
    c0 = x1*cc - x2*sn;
    c1 = x1*sn + x2*cc;
}

// fp16 mma GEMM: acc[M,N] = A[M,K]@B[N,K]^T (fp32 accum), 128x128x64, 3-stage, m16n8k16.
// modes: 0 Cf=acc; 2 Cf=acc+Gf (residual); 3 Cf=rope(acc) (qkv epilogue)
#define HROW 72
#define HSTG_B (128*144)
#define MG_STAGES 3
#define MG_SMEM (MG_STAGES*2*HSTG_B)
__global__ void __launch_bounds__(256,2) mgemm_kernel(
    const __half* __restrict__ A, const __half* __restrict__ B,
    float* __restrict__ Cf, const float* __restrict__ Gf,
    int N, int K, const int* __restrict__ perm, const int* __restrict__ off,
    long long strideB, int mode)
{
    extern __shared__ char smc[];
    int row0 = blockIdx.y * 128;
    int col0 = blockIdx.x * 128;
    if (off) {
        if (row0 >= off[NEXP]) return;
        int e = 0;
        #pragma unroll
        for (int i=1; i<NEXP; i++) if (row0 >= off[i]) e = i;
        B += (long long)e * strideB;
    }
    int tid = threadIdx.x, wid = tid >> 5, lane = tid & 31;
    int r = lane >> 2, cq = lane & 3;
    int wm = (wid & 3) * 32, wn = (wid >> 2) * 64;
    uint32_t sbase = smem_u32(smc);

    int j = tid & 7, rg = tid >> 3;
    const char* gA[4]; uint32_t szA[4]; const char* gB[4]; uint32_t sOf[4];
    #pragma unroll
    for (int i=0;i<4;i++) {
        int rr = rg + i*32;
        sOf[i] = (uint32_t)(rr*144 + j*16);
        int ar = row0 + rr; uint32_t sz = 16;
        if (perm) { int pr = perm[ar]; if (pr < 0) { ar = 0; sz = 0; } else ar = pr; }
        gA[i] = (const char*)(A + (size_t)ar * K) + j*16;
        szA[i] = sz;
        gB[i] = (const char*)(B + (size_t)(col0 + rr) * K) + j*16;
    }

    float acc[2][8][4];
    #pragma unroll
    for (int mt=0;mt<2;mt++)
        #pragma unroll
        for (int nt=0;nt<8;nt++)
            #pragma unroll
            for (int q=0;q<4;q++) acc[mt][nt][q] = 0.f;

    int NC = K >> 6;

    #pragma unroll
    for (int pre=0; pre<2; pre++) {
        uint32_t st = sbase + (uint32_t)(pre * 2*HSTG_B);
        size_t ko = (size_t)pre * 128;
        #pragma unroll
        for (int i=0;i<4;i++) cp16(st + sOf[i], gA[i] + ko, szA[i]);
        #pragma unroll
        for (int i=0;i<4;i++) cp16(st + HSTG_B + sOf[i], gB[i] + ko, 16);
        asm volatile("cp.async.commit_group;" ::: "memory");
    }

    #pragma unroll 1
    for (int c = 0; c < NC; ++c) {
        if (c + 2 < NC) {
            uint32_t st = sbase + (uint32_t)(((c+2)%MG_STAGES) * 2*HSTG_B);
            size_t ko = (size_t)(c+2) * 128;
            #pragma unroll
            for (int i=0;i<4;i++) cp16(st + sOf[i], gA[i] + ko, szA[i]);
            #pragma unroll
            for (int i=0;i<4;i++) cp16(st + HSTG_B + sOf[i], gB[i] + ko, 16);
            asm volatile("cp.async.commit_group;" ::: "memory");
            asm volatile("cp.async.wait_group 2;" ::: "memory");
        } else if (c + 1 < NC) {
            asm volatile("cp.async.wait_group 1;" ::: "memory");
        } else {
            asm volatile("cp.async.wait_group 0;" ::: "memory");
        }
        __syncthreads();
        const __half* sa = (const __half*)(smc + (c%MG_STAGES)*2*HSTG_B);
        const __half* sb = (const __half*)(smc + (c%MG_STAGES)*2*HSTG_B + HSTG_B);
        #pragma unroll
        for (int ks=0; ks<4; ks++) {
            int kk = ks*16 + cq*2;
            uint32_t a[2][4];
            #pragma unroll
            for (int mt=0;mt<2;mt++) {
                int m = wm + mt*16 + r;
                a[mt][0] = *(const uint32_t*)(sa + m*HROW + kk);
                a[mt][1] = *(const uint32_t*)(sa + (m+8)*HROW + kk);
                a[mt][2] = *(const uint32_t*)(sa + m*HROW + kk + 8);
                a[mt][3] = *(const uint32_t*)(sa + (m+8)*HROW + kk + 8);
            }
            #pragma unroll
            for (int nt=0;nt<8;nt++) {
                int n = wn + nt*8 + r;
                uint32_t b0 = *(const uint32_t*)(sb + n*HROW + kk);
                uint32_t b1 = *(const uint32_t*)(sb + n*HROW + kk + 8);
                mma16h(acc[0][nt], a[0][0], a[0][1], a[0][2], a[0][3], b0, b1);
                mma16h(acc[1][nt], a[1][0], a[1][1], a[1][2], a[1][3], b0, b1);
            }
        }
        __syncthreads();
    }

    #pragma unroll
    for (int mt=0;mt<2;mt++) {
        #pragma unroll
        for (int nt=0;nt<8;nt++) {
            int row = row0 + wm + mt*16 + r;
            int col = col0 + wn + nt*8 + cq*2;
            long long i0 = (long long)row*N + col, i1 = (long long)(row+8)*N + col;
            if (mode == 0) {
                *(float2*)(Cf + i0) = make_float2(acc[mt][nt][0], acc[mt][nt][1]);
                *(float2*)(Cf + i1) = make_float2(acc[mt][nt][2], acc[mt][nt][3]);
            } else if (mode == 2) {
                float2 r0 = *(const float2*)(Gf + i0);
                float2 r1 = *(const float2*)(Gf + i1);
                *(float2*)(Cf + i0) = make_float2(acc[mt][nt][0]+r0.x, acc[mt][nt][1]+r0.y);
                *(float2*)(Cf + i1) = make_float2(acc[mt][nt][2]+r1.x, acc[mt][nt][3]+r1.y);
            } else { // mode 3: rope
                float c0 = acc[mt][nt][0], c1 = acc[mt][nt][1];
                float c2 = acc[mt][nt][2], c3 = acc[mt][nt][3];
                if (col < DMODEL + KVDIM) {
                    rope_pair(row,   col, c0, c1);
                    rope_pair(row+8, col, c2, c3);
                }
                *(float2*)(Cf + i0) = make_float2(c0, c1);
                *(float2*)(Cf + i1) = make_float2(c2, c3);
            }
        }
    }
}

// fused g+u grouped GEMM: 128(M)x64(N) tile; writes Hh = silu(g)*u in fp16.
__global__ void __launch_bounds__(256,2) gugemm_kernel(
    const __half* __restrict__ A, const __half* __restrict__ Bg, const __half* __restrict__ Bu,
    __half* __restrict__ Ch, int N, int K,
    const int* __restrict__ perm, const int* __restrict__ off, long long strideB)
{
    extern __shared__ char smc[];
    int row0 = blockIdx.y * 128;
    int col0 = blockIdx.x * 64;
    if (row0 >= off[NEXP]) return;
    {
        int e = 0;
        #pragma unroll
        for (int i=1; i<NEXP; i++) if (row0 >= off[i]) e = i;
        Bg += (long long)e * strideB;
        Bu += (long long)e * strideB;
    }
    int tid = threadIdx.x, wid = tid >> 5, lane = tid & 31;
    int r = lane >> 2, cq = lane & 3;
    int wm = (wid & 3) * 32, wn = (wid >> 2) * 32;
    uint32_t sbase = smem_u32(smc);

    int j = tid & 7, rg = tid >> 3;
    const char* gA[4]; uint32_t szA[4]; const char* gB[4]; uint32_t sOf[4];
    #pragma unroll
    for (int i=0;i<4;i++) {
        int rr = rg + i*32;
        sOf[i] = (uint32_t)(rr*144 + j*16);
        int ar = row0 + rr; uint32_t sz = 16;
        int pr = perm[ar]; if (pr < 0) { ar = 0; sz = 0; } else ar = pr;
        gA[i] = (const char*)(A + (size_t)ar * K) + j*16;
        szA[i] = sz;
        gB[i] = (rr < 64) ? (const char*)(Bg + (size_t)(col0 + rr) * K) + j*16
                          : (const char*)(Bu + (size_t)(col0 + rr - 64) * K) + j*16;
    }

    float accg[2][4][4], accu[2][4][4];
    #pragma unroll
    for (int mt=0;mt<2;mt++)
        #pragma unroll
        for (int nt=0;nt<4;nt++)
            #pragma unroll
            for (int q=0;q<4;q++) { accg[mt][nt][q] = 0.f; accu[mt][nt][q] = 0.f; }

    int NC = K >> 6;

    #pragma unroll
    for (int pre=0; pre<2; pre++) {
        uint32_t st = sbase + (uint32_t)(pre * 2*HSTG_B);
        size_t ko = (size_t)pre * 128;
        #pragma unroll
        for (int i=0;i<4;i++) cp16(st + sOf[i], gA[i] + ko, szA[i]);
        #pragma unroll
        for (int i=0;i<4;i++) cp16(st + HSTG_B + sOf[i], gB[i] + ko, 16);
        asm volatile("cp.async.commit_group;" ::: "memory");
    }

    #pragma unroll 1
    for (int c = 0; c < NC; ++c) {
        if (c + 2 < NC) {
            uint32_t st = sbase + (uint32_t)(((c+2)%MG_STAGES) * 2*HSTG_B);
            size_t ko = (size_t)(c+2) * 128;
            #pragma unroll
            for (int i=0;i<4;i++) cp16(st + sOf[i], gA[i] + ko, szA[i]);
            #pragma unroll
            for (int i=0;i<4;i++) cp16(st + HSTG_B + sOf[i], gB[i] + ko, 16);
            asm volatile("cp.async.commit_group;" ::: "memory");
            asm volatile("cp.async.wait_group 2;" ::: "memory");
        } else if (c + 1 < NC) {
            asm volatile("cp.async.wait_group 1;" ::: "memory");
        } else {
            asm volatile("cp.async.wait_group 0;" ::: "memory");
        }
        __syncthreads();
        const __half* sa = (const __half*)(smc + (c%MG_STAGES)*2*HSTG_B);
        const __half* sb = (const __half*)(smc + (c%MG_STAGES)*2*HSTG_B + HSTG_B);
        #pragma unroll
        for (int ks=0; ks<4; ks++) {
            int kk = ks*16 + cq*2;
            uint32_t a[2][4];
            #pragma unroll
            for (int mt=0;mt<2;mt++) {
                int m = wm + mt*16 + r;
                a[mt][0] = *(const uint32_t*)(sa + m*HROW + kk);
                a[mt][1] = *(const uint32_t*)(sa + (m+8)*HROW + kk);
                a[mt][2] = *(const uint32_t*)(sa + m*HROW + kk + 8);
                a[mt][3] = *(const uint32_t*)(sa + (m+8)*HROW + kk + 8);
            }
            #pragma unroll
            for (int nt=0;nt<4;nt++) {
                int n = wn + nt*8 + r;
                uint32_t bg0 = *(const uint32_t*)(sb + n*HROW + kk);
                uint32_t bg1 = *(const uint32_t*)(sb + n*HROW + kk + 8);
                uint32_t bu0 = *(const uint32_t*)(sb + (n+64)*HROW + kk);
                uint32_t bu1 = *(const uint32_t*)(sb + (n+64)*HROW + kk + 8);
                mma16h(accg[0][nt], a[0][0], a[0][1], a[0][2], a[0][3], bg0, bg1);
                mma16h(accg[1][nt], a[1][0], a[1][1], a[1][2], a[1][3], bg0, bg1);
                mma16h(accu[0][nt], a[0][0], a[0][1], a[0][2], a[0][3], bu0, bu1);
                mma16h(accu[1][nt], a[1][0], a[1][1], a[1][2], a[1][3], bu0, bu1);
            }
        }
        __syncthreads();
    }

    #pragma unroll
    for (int mt=0;mt<2;mt++) {
        #pragma unroll
        for (int nt=0;nt<4;nt++) {
            int row = row0 + wm + mt*16 + r;
            int col = col0 + wn + nt*8 + cq*2;
            *(__half2*)(Ch + (long long)row*N + col) = __floats2half2_rn(
                silu(accg[mt][nt][0])*accu[mt][nt][0], silu(accg[mt][nt][1])*accu[mt][nt][1]);
            *(__half2*)(Ch + (long long)(row+8)*N + col) = __floats2half2_rn(
                silu(accg[mt][nt][2])*accu[mt][nt][2], silu(accg[mt][nt][3])*accu[mt][nt][3]);
        }
    }
}

// flash attention: 2 threads per query, warp-UNIFORM inner loop (causal masking
// via s=-inf, keeps the pair-shuffle convergent). fp32 math, split fp16 output.
__global__ __launch_bounds__(128) void attn_kernel(
    const float* __restrict__ QKV, __half* __restrict__ Os)
{
    __shared__ float Ks[64][64];
    __shared__ float Vs[64][64];
    int tid = threadIdx.x;              // 0..127
    int qloc = tid >> 1;                // query within tile
    int hf   = tid & 1;                 // head-dim half
    int q0 = blockIdx.x * 64;
    int h  = blockIdx.y;
    int b  = blockIdx.z;
    int kvh = h >> 2;
    int qi = q0 + qloc;
    long long t = (long long)b*SEQ + qi;
    float q[32], o[32];
    const float4* qp = (const float4*)(QKV + t*QKVN + h*HD + hf*32);
    #pragma unroll
    for (int i=0;i<8;i++) {
        float4 f = qp[i];
        q[4*i]=f.x*0.125f; q[4*i+1]=f.y*0.125f; q[4*i+2]=f.z*0.125f; q[4*i+3]=f.w*0.125f;
    }
    #pragma unroll
    for (int d=0; d<32; d++) o[d] = 0.f;
    float m = -1e30f, l = 0.f;
    int ntiles = q0/64 + 1;
    for (int kt=0; kt<ntiles; kt++) {
        for (int idx=tid; idx<64*16; idx+=128) {
            int rr = idx >> 4, cc = idx & 15;
            long long base = ((long long)(b*SEQ + kt*64 + rr))*QKVN + DMODEL + kvh*HD + cc*4;
            *(float4*)&Ks[rr][cc*4] = *(const float4*)(QKV + base);
            *(float4*)&Vs[rr][cc*4] = *(const float4*)(QKV + base + KVDIM);
        }
        __syncthreads();
        bool diag = (kt == q0/64);
        int kbase = kt*64;
        #pragma unroll 2
        for (int jj=0; jj<64; jj++) {
            float s0=0.f,s1=0.f,s2=0.f,s3=0.f;
            const float4* kr = (const float4*)&Ks[jj][hf*32];
            #pragma unroll
            for (int i=0;i<8;i++) {
                float4 kv4 = kr[i];
                s0 += q[4*i]*kv4.x; s1 += q[4*i+1]*kv4.y;
                s2 += q[4*i+2]*kv4.z; s3 += q[4*i+3]*kv4.w;
            }
            float sp = (s0+s1)+(s2+s3);
            float s = sp + __shfl_xor_sync(0xffffffffu, sp, 1);
            if (diag && (kbase + jj > qi)) s = -1e30f;   // causal mask (uniform loop)
            if (s > m) {
                float corr = __expf(m - s);
                l *= corr;
                #pragma unroll
                for (int d=0; d<32; d++) o[d] *= corr;
                m = s;
            }
            float p = __expf(s - m);
            l += p;
            const float4* vr = (const float4*)&Vs[jj][hf*32];
            #pragma unroll
            for (int i=0;i<8;i++) {
                float4 vv = vr[i];
                o[4*i] += p*vv.x; o[4*i+1] += p*vv.y;
                o[4*i+2] += p*vv.z; o[4*i+3] += p*vv.w;
            }
        }
        __syncthreads();
    }
    float inv = 1.f / l;
    __half2* d = (__half2*)(Os + (size_t)t*K3);
    #pragma unroll
    for (int i=0;i<8;i++) {
        int c = h*HD + hf*32 + 4*i;
        float vx = o[4*i]*inv, vy = o[4*i+1]*inv, vz = o[4*i+2]*inv, vw = o[4*i+3]*inv;
        __half2 h0,l0,h1,l1;
        split2(vx, vy, h0, l0);
        split2(vz, vw, h1, l1);
        d[c/2] = h0;              d[c/2+1] = h1;
        d[(DMODEL+c)/2] = l0;     d[(DMODEL+c)/2+1] = l1;
        d[(2*DMODEL+c)/2] = h0;   d[(2*DMODEL+c)/2+1] = h1;
    }
}

__global__ void router_kernel(const float* __restrict__ XN, const float* __restrict__ RW) {
    __shared__ float sw[NEXP*DMODEL];
    int tid = threadIdx.x;
    for (int i=tid; i<NEXP*DMODEL/4; i+=256)
        ((float4*)sw)[i] = ((const float4*)RW)[i];
    __syncthreads();
    int warp = tid >> 5, lane = tid & 31;
    int token = blockIdx.x*8 + warp;
    const float* xr = XN + (long long)token*DMODEL;
    float acc[NEXP];
    #pragma unroll
    for (int e=0;e<NEXP;e++) acc[e]=0.f;
    for (int d=lane; d<DMODEL; d+=32) {
        float xv = xr[d];
        #pragma unroll
        for (int e=0;e<NEXP;e++) acc[e] += xv * sw[e*DMODEL + d];
    }
    #pragma unroll
    for (int e=0;e<NEXP;e++)
        #pragma unroll
        for (int off=16; off; off>>=1) acc[e] += __shfl_xor_sync(0xffffffffu, acc[e], off);
    if (lane == 0) {
        float mx = acc[0];
        #pragma unroll
        for (int e=1;e<NEXP;e++) mx = fmaxf(mx, acc[e]);
        float pe[NEXP], sum = 0.f;
        #pragma unroll
        for (int e=0;e<NEXP;e++) { pe[e] = expf(acc[e]-mx); sum += pe[e]; }
        float inv = 1.f/sum;
        #pragma unroll
        for (int e=0;e<NEXP;e++) { pe[e] *= inv; g_probs_all[token*NEXP+e] = pe[e]; }
        int e1 = 0; float p1 = pe[0];
        #pragma unroll
        for (int e=1;e<NEXP;e++) if (pe[e] > p1) { p1 = pe[e]; e1 = e; }
        int e2 = -1; float p2 = -1.f;
        #pragma unroll
        for (int e=0;e<NEXP;e++) if (e != e1 && pe[e] > p2) { p2 = pe[e]; e2 = e; }
        float rn = 1.f/(p1+p2);
        g_topk_e[token*2]   = e1;  g_topk_e[token*2+1] = e2;
        g_topk_p[token*2]   = p1*rn; g_topk_p[token*2+1] = p2*rn;
        atomicAdd(&g_cnt[e1], 1);
        atomicAdd(&g_cnt[e2], 1);
    }
}

__global__ void psum_kernel() {
    int e = blockIdx.x;
    int tid = threadIdx.x;
    float acc = 0.f;
    for (int t=tid; t<NTOK; t+=256) acc += g_probs_all[t*NEXP + e];
    #pragma unroll
    for (int off=16; off; off>>=1) acc += __shfl_xor_sync(0xffffffffu, acc, off);
    __shared__ float red[8];
    if ((tid & 31) == 0) red[tid>>5] = acc;
    __syncthreads();
    if (tid < 8) {
        float v = red[tid];
        #pragma unroll
        for (int off=4; off; off>>=1) v += __shfl_xor_sync(0xffu, v, off);
        if (tid == 0) g_Psum[e] = v;
    }
}

__global__ void finalize_kernel(float* __restrict__ out, int out_size) {
    if (threadIdx.x == 0 && blockIdx.x == 0) {
        int total = 0;
        for (int e=0; e<NEXP; e++) {
            g_off[e] = total; g_cur[e] = total;
            total += ((g_cnt[e] + 127)/128)*128;
        }
        g_off[NEXP] = total;
        float aux = 0.f;
        for (int e=0; e<NEXP; e++)
            aux += ((float)g_cnt[e] / (float)NSLOT) * (g_Psum[e] / (float)NTOK);
        out[out_size-9] = (float)NEXP * aux;
        for (int e=0; e<NEXP; e++) out[out_size-8+e] = (float)g_cnt[e];
    }
}

__global__ void assign_kernel() {
    int token = blockIdx.x*256 + threadIdx.x;
    if (token >= NTOK) return;
    #pragma unroll
    for (int kk=0; kk<TOPK; kk++) {
        int e = g_topk_e[token*2+kk];
        int pos = atomicAdd(&g_cur[e], 1);
        g_perm[pos] = token;
        g_prob[pos] = g_topk_p[token*2+kk];
        g_posOf[token*2+kk] = pos;
    }
}

__global__ void combine_kernel(float* __restrict__ out) {
    int t = blockIdx.x;
    int tid = threadIdx.x;
    int p1i = g_posOf[t*2], p2i = g_posOf[t*2+1];
    float p1 = g_prob[p1i], p2 = g_prob[p2i];
    float4 a  = ((const float4*)(g_x1 + (long long)t*DMODEL))[tid];
    float4 y1 = ((const float4*)(g_Y  + (long long)p1i*DMODEL))[tid];
    float4 y2 = ((const float4*)(g_Y  + (long long)p2i*DMODEL))[tid];
    ((float4*)(out + (long long)t*DMODEL))[tid] = make_float4(
        a.x + p1*y1.x + p2*y2.x, a.y + p1*y1.y + p2*y2.y,
        a.z + p1*y1.z + p2*y2.z, a.w + p1*y1.w + p2*y2.w);
}

extern "C" void kernel_launch(void* const* d_in, const int* in_sizes, int n_in,
                              void* d_out, int out_size) {
    const float* x        = (const float*)d_in[0];
    const float* wq       = (const float*)d_in[1];
    const float* wk       = (const float*)d_in[2];
    const float* wv       = (const float*)d_in[3];
    const float* wo       = (const float*)d_in[4];
    const float* attn_nw  = (const float*)d_in[5];
    const float* ffn_nw   = (const float*)d_in[6];
    const float* router_w = (const float*)d_in[7];
    const float* Wg       = (const float*)d_in[8];
    const float* Wu       = (const float*)d_in[9];
    const float* Wd       = (const float*)d_in[10];
    float* out = (float*)d_out;

    float *p_xn,*p_qkv,*p_x1,*p_Y;
    __half *p_xns,*p_xnt,*p_attns,*p_Wqkvs,*p_Wos,*p_Hh,*p_Wgt,*p_Wut,*p_Wdt;
    int *p_perm, *p_off;
    cudaGetSymbolAddress((void**)&p_xn,   g_xn);
    cudaGetSymbolAddress((void**)&p_xns,  g_xns);
    cudaGetSymbolAddress((void**)&p_xnt,  g_xnt);
    cudaGetSymbolAddress((void**)&p_qkv,  g_qkv);
    cudaGetSymbolAddress((void**)&p_attns,g_attns);
    cudaGetSymbolAddress((void**)&p_x1,   g_x1);
    cudaGetSymbolAddress((void**)&p_Hh,   g_Hh);
    cudaGetSymbolAddress((void**)&p_Y,    g_Y);
    cudaGetSymbolAddress((void**)&p_Wqkvs,g_Wqkvs);
    cudaGetSymbolAddress((void**)&p_Wos,  g_Wos);
    cudaGetSymbolAddress((void**)&p_Wgt,  g_Wgt);
    cudaGetSymbolAddress((void**)&p_Wut,  g_Wut);
    cudaGetSymbolAddress((void**)&p_Wdt,  g_Wdt);
    cudaGetSymbolAddress((void**)&p_perm, g_perm);
    cudaGetSymbolAddress((void**)&p_off,  g_off);

    cudaFuncSetAttribute(mgemm_kernel, cudaFuncAttributeMaxDynamicSharedMemorySize, MG_SMEM);
    cudaFuncSetAttribute(gugemm_kernel, cudaFuncAttributeMaxDynamicSharedMemorySize, MG_SMEM);

    // attn_kernel stays at launch index 3 (ncu profiles idx 3)
    rmsnorm_kernel<<<NTOK, 256>>>(x, attn_nw, nullptr, nullptr, p_xns);            // 0
    cvtsplit3_kernel<<<(NWQ+2*NWK+255)/256, 256>>>(
        (const float4*)wq, (const float4*)wk, (const float4*)wv, p_Wqkvs);         // 1
    mgemm_kernel<<<dim3(QKVN/128, NTOK/128), 256, MG_SMEM>>>(
        p_xns, p_Wqkvs, p_qkv, nullptr, QKVN, K3, nullptr, nullptr, 0, 3);         // 2 (qkv + fused rope)
    attn_kernel<<<dim3(SEQ/64, NHEADS, BATCH), 128>>>(p_qkv, p_attns);             // 3 <- profiled

    init_kernel<<<(NSLOT_PAD+255)/256, 256>>>();

    cvtsplit_kernel<<<(DMODEL*DMODEL/4+255)/256, 256>>>((const float4*)wo, p_Wos, DMODEL, DMODEL*DMODEL/4);

    mgemm_kernel<<<dim3(DMODEL/128, NTOK/128), 256, MG_SMEM>>>(
        p_attns, p_Wos, p_x1, x, DMODEL, K3, nullptr, nullptr, 0, 2);

    rmsnorm_kernel<<<NTOK, 256>>>(p_x1, ffn_nw, p_xn, p_xnt, nullptr);

    router_kernel<<<NTOK/8, 256>>>(p_xn, router_w);
    psum_kernel<<<NEXP, 256>>>();
    finalize_kernel<<<1, 32>>>(out, out_size);
    assign_kernel<<<NTOK/256, 256>>>();

    const int nW = NEXP*DFF*DMODEL/4;
    cvth_kernel<<<(nW+255)/256, 256>>>((const float4*)Wg, (__half2*)p_Wgt, nW);
    cvth_kernel<<<(nW+255)/256, 256>>>((const float4*)Wu, (__half2*)p_Wut, nW);
    cvth_kernel<<<(nW+255)/256, 256>>>((const float4*)Wd, (__half2*)p_Wdt, nW);

    gugemm_kernel<<<dim3(DFF/64, NSLOT_PAD/128), 256, MG_SMEM>>>(
        p_xnt, p_Wgt, p_Wut, p_Hh, DFF, DMODEL, p_perm, p_off, (long long)DFF*DMODEL);
    mgemm_kernel<<<dim3(DMODEL/128, NSLOT_PAD/128), 256, MG_SMEM>>>(
        p_Hh, p_Wdt, p_Y, nullptr, DMODEL, DFF, nullptr, p_off, (long long)DMODEL*DFF, 0);

    combine_kernel<<<NTOK, 256>>>(out);
}

// round 15
// speedup vs baseline: 1.2439x; 1.2439x over previous
#include <cuda_runtime.h>
#include <cuda_fp16.h>
#include <math.h>
#include <stdint.h>

#define BATCH 2
#define SEQ 2048
#define NTOK (BATCH*SEQ)
#define DMODEL 1024
#define DFF 2048
#define NHEADS 16
#define NKVHEADS 4
#define HD 64
#define KVDIM (NKVHEADS*HD)
#define QKVN (DMODEL+2*KVDIM)   // 1536
#define K3 (3*DMODEL)           // 3072 split-K
#define NEXP 8
#define TOPK 2
#define NSLOT (NTOK*TOPK)
#define NSLOT_PAD 9216

__device__ float  g_xn[NTOK*DMODEL];
__device__ __half g_xns[NTOK*K3];
__device__ __half g_xnt[NTOK*DMODEL];
__device__ float  g_qkv[NTOK*QKVN];
__device__ __half g_attns[NTOK*K3];
__device__ float  g_x1[NTOK*DMODEL];
__device__ __half g_Hh[NSLOT_PAD*DFF];
__device__ float  g_Y[NSLOT_PAD*DMODEL];
__device__ __half g_Wqkvs[QKVN*K3];
__device__ __half g_Wos[DMODEL*K3];
__device__ __half g_Wgt[NEXP*DFF*DMODEL];
__device__ __half g_Wut[NEXP*DFF*DMODEL];
__device__ __half g_Wdt[NEXP*DMODEL*DFF];
__device__ int    g_perm[NSLOT_PAD];
__device__ float  g_prob[NSLOT_PAD];
__device__ int    g_posOf[NTOK*TOPK];
__device__ int    g_topk_e[NTOK*TOPK];
__device__ float  g_topk_p[NTOK*TOPK];
__device__ float  g_probs_all[NTOK*NEXP];
__device__ int    g_cnt[NEXP];
__device__ int    g_off[NEXP+1];
__device__ int    g_cur[NEXP];
__device__ float  g_Psum[NEXP];

__device__ __forceinline__ void cp16(uint32_t dst, const void* src, uint32_t sz) {
    asm volatile("cp.async.cg.shared.global [%0], [%1], 16, %2;" :: "r"(dst), "l"(src), "r"(sz) : "memory");
}
__device__ __forceinline__ uint32_t smem_u32(const void* p) {
    uint32_t a;
    asm("{ .reg .u64 t; cvta.to.shared.u64 t, %1; cvt.u32.u64 %0, t; }" : "=r"(a) : "l"(p));
    return a;
}
__device__ __forceinline__ void mma16h(float* c, uint32_t a0, uint32_t a1, uint32_t a2,
                                       uint32_t a3, uint32_t b0, uint32_t b1) {
    asm volatile("mma.sync.aligned.m16n8k16.row.col.f32.f16.f16.f32 "
        "{%0,%1,%2,%3}, {%4,%5,%6,%7}, {%8,%9}, {%0,%1,%2,%3};"
        : "+f"(c[0]), "+f"(c[1]), "+f"(c[2]), "+f"(c[3])
        : "r"(a0), "r"(a1), "r"(a2), "r"(a3), "r"(b0), "r"(b1));
}
__device__ __forceinline__ float silu(float g) { return g / (1.f + __expf(-g)); }
__device__ __forceinline__ void split2(float x, float y, __half2& h, __half2& l) {
    __half hx = __float2half_rn(x), hy = __float2half_rn(y);
    h = __halves2half2(hx, hy);
    l = __floats2half2_rn(x - __half2float(hx), y - __half2float(hy));
}

__global__ void init_kernel() {
    int i = blockIdx.x*256 + threadIdx.x;
    if (i < NSLOT_PAD) g_perm[i] = -1;
    if (i < NEXP) { g_cnt[i] = 0; g_Psum[i] = 0.f; }
}

__global__ void cvth_kernel(const float4* __restrict__ src, __half2* __restrict__ dst, int n4) {
    int i = blockIdx.x*256 + threadIdx.x;
    if (i < n4) {
        float4 v = src[i];
        dst[2*i]   = __floats2half2_rn(v.x, v.y);
        dst[2*i+1] = __floats2half2_rn(v.z, v.w);
    }
}

__device__ __forceinline__ void cvtsplit_one(const float4* src, __half* dst, int K, int i) {
    int kq = K >> 2;
    int n = i / kq, c = (i - n*kq) * 4;
    float4 v = src[i];
    __half2 h0, l0, h1, l1;
    split2(v.x, v.y, h0, l0);
    split2(v.z, v.w, h1, l1);
    __half2* d = (__half2*)(dst + (size_t)n*3*K);
    d[c/2] = h0;         d[c/2+1] = h1;
    d[(K+c)/2] = h0;     d[(K+c)/2+1] = h1;
    d[(2*K+c)/2] = l0;   d[(2*K+c)/2+1] = l1;
}

__global__ void cvtsplit_kernel(const float4* __restrict__ src, __half* __restrict__ dst,
                                int K, int n4) {
    int i = blockIdx.x*256 + threadIdx.x;
    if (i < n4) cvtsplit_one(src, dst, K, i);
}

#define NWQ (DMODEL*DMODEL/4)
#define NWK (KVDIM*DMODEL/4)
__global__ void cvtsplit3_kernel(const float4* __restrict__ wq, const float4* __restrict__ wk,
                                 const float4* __restrict__ wv, __half* __restrict__ dst) {
    int i = blockIdx.x*256 + threadIdx.x;
    if (i < NWQ) {
        cvtsplit_one(wq, dst, DMODEL, i);
    } else if (i < NWQ + NWK) {
        cvtsplit_one(wk, dst + (size_t)DMODEL*K3, DMODEL, i - NWQ);
    } else if (i < NWQ + 2*NWK) {
        cvtsplit_one(wv, dst + (size_t)(DMODEL+KVDIM)*K3, DMODEL, i - NWQ - NWK);
    }
}

__global__ void rmsnorm_kernel(const float* __restrict__ X, const float* __restrict__ W,
                               float* __restrict__ Y, __half* __restrict__ Yt,
                               __half* __restrict__ Ys) {
    int t = blockIdx.x;
    int tid = threadIdx.x;
    float4 xv = ((const float4*)(X + (long long)t*DMODEL))[tid];
    float ss = xv.x*xv.x + xv.y*xv.y + xv.z*xv.z + xv.w*xv.w;
    #pragma unroll
    for (int off=16; off; off>>=1) ss += __shfl_xor_sync(0xffffffffu, ss, off);
    __shared__ float red[8];
    if ((tid & 31) == 0) red[tid>>5] = ss;
    __syncthreads();
    if (tid < 8) {
        float v = red[tid];
        #pragma unroll
        for (int off=4; off; off>>=1) v += __shfl_xor_sync(0xffu, v, off);
        if (tid == 0) red[0] = v;
    }
    __syncthreads();
    float r = rsqrtf(red[0]/(float)DMODEL + 1e-6f);
    float4 wv = ((const float4*)W)[tid];
    float4 o = make_float4(xv.x*r*wv.x, xv.y*r*wv.y, xv.z*r*wv.z, xv.w*r*wv.w);
    if (Y) ((float4*)(Y + (long long)t*DMODEL))[tid] = o;
    if (Yt) {
        __half2* yh = (__half2*)(Yt + (long long)t*DMODEL);
        yh[2*tid]   = __floats2half2_rn(o.x, o.y);
        yh[2*tid+1] = __floats2half2_rn(o.z, o.w);
    }
    if (Ys) {
        int c = 4*tid;
        __half2 h0,l0,h1,l1;
        split2(o.x, o.y, h0, l0);
        split2(o.z, o.w, h1, l1);
        __half2* d = (__half2*)(Ys + (size_t)t*K3);
        d[c/2] = h0;              d[c/2+1] = h1;
        d[(DMODEL+c)/2] = l0;     d[(DMODEL+c)/2+1] = l1;
        d[(2*DMODEL+c)/2] = h0;   d[(2*DMODEL+c)/2+1] = h1;
    }
}

__device__ __forceinline__ void rope_pair(int row, int col, float& c0, float& c1) {
    int s = row & (SEQ-1);
    int elem = col & 63;
    float f = (float)(elem & 31);
    float freq = powf(10000.f, -f/32.f);
    float ang = (float)s * freq;
    float cc = cosf(ang), sn = sinf(ang);
    float x1 = c0, x2 = c1;
    c0 = x1*cc - x2*sn;
    c1 = x1*sn + x2*cc;
}

// fp16 mma GEMM: acc[M,N] = A[M,K]@B[N,K]^T (fp32 accum), 128x128x64, 3-stage, m16n8k16.
// modes: 0 Cf=acc; 2 Cf=acc+Gf (residual); 3 Cf=rope(acc) (qkv epilogue)
#define HROW 72
#define HSTG_B (128*144)
#define MG_STAGES 3
#define MG_SMEM (MG_STAGES*2*HSTG_B)
__global__ void __launch_bounds__(256,2) mgemm_kernel(
    const __half* __restrict__ A, const __half* __restrict__ B,
    float* __restrict__ Cf, const float* __restrict__ Gf,
    int N, int K, const int* __restrict__ perm, const int* __restrict__ off,
    long long strideB, int mode)
{
    extern __shared__ char smc[];
    int row0 = blockIdx.y * 128;
    int col0 = blockIdx.x * 128;
    if (off) {
        if (row0 >= off[NEXP]) return;
        int e = 0;
        #pragma unroll
        for (int i=1; i<NEXP; i++) if (row0 >= off[i]) e = i;
        B += (long long)e * strideB;
    }
    int tid = threadIdx.x, wid = tid >> 5, lane = tid & 31;
    int r = lane >> 2, cq = lane & 3;
    int wm = (wid & 3) * 32, wn = (wid >> 2) * 64;
    uint32_t sbase = smem_u32(smc);

    int j = tid & 7, rg = tid >> 3;
    const char* gA[4]; uint32_t szA[4]; const char* gB[4]; uint32_t sOf[4];
    #pragma unroll
    for (int i=0;i<4;i++) {
        int rr = rg + i*32;
        sOf[i] = (uint32_t)(rr*144 + j*16);
        int ar = row0 + rr; uint32_t sz = 16;
        if (perm) { int pr = perm[ar]; if (pr < 0) { ar = 0; sz = 0; } else ar = pr; }
        gA[i] = (const char*)(A + (size_t)ar * K) + j*16;
        szA[i] = sz;
        gB[i] = (const char*)(B + (size_t)(col0 + rr) * K) + j*16;
    }

    float acc[2][8][4];
    #pragma unroll
    for (int mt=0;mt<2;mt++)
        #pragma unroll
        for (int nt=0;nt<8;nt++)
            #pragma unroll
            for (int q=0;q<4;q++) acc[mt][nt][q] = 0.f;

    int NC = K >> 6;

    #pragma unroll
    for (int pre=0; pre<2; pre++) {
        uint32_t st = sbase + (uint32_t)(pre * 2*HSTG_B);
        size_t ko = (size_t)pre * 128;
        #pragma unroll
        for (int i=0;i<4;i++) cp16(st + sOf[i], gA[i] + ko, szA[i]);
        #pragma unroll
        for (int i=0;i<4;i++) cp16(st + HSTG_B + sOf[i], gB[i] + ko, 16);
        asm volatile("cp.async.commit_group;" ::: "memory");
    }

    #pragma unroll 1
    for (int c = 0; c < NC; ++c) {
        if (c + 2 < NC) {
            uint32_t st = sbase + (uint32_t)(((c+2)%MG_STAGES) * 2*HSTG_B);
            size_t ko = (size_t)(c+2) * 128;
            #pragma unroll
            for (int i=0;i<4;i++) cp16(st + sOf[i], gA[i] + ko, szA[i]);
            #pragma unroll
            for (int i=0;i<4;i++) cp16(st + HSTG_B + sOf[i], gB[i] + ko, 16);
            asm volatile("cp.async.commit_group;" ::: "memory");
            asm volatile("cp.async.wait_group 2;" ::: "memory");
        } else if (c + 1 < NC) {
            asm volatile("cp.async.wait_group 1;" ::: "memory");
        } else {
            asm volatile("cp.async.wait_group 0;" ::: "memory");
        }
        __syncthreads();
        const __half* sa = (const __half*)(smc + (c%MG_STAGES)*2*HSTG_B);
        const __half* sb = (const __half*)(smc + (c%MG_STAGES)*2*HSTG_B + HSTG_B);
        #pragma unroll
        for (int ks=0; ks<4; ks++) {
            int kk = ks*16 + cq*2;
            uint32_t a[2][4];
            #pragma unroll
            for (int mt=0;mt<2;mt++) {
                int m = wm + mt*16 + r;
                a[mt][0] = *(const uint32_t*)(sa + m*HROW + kk);
                a[mt][1] = *(const uint32_t*)(sa + (m+8)*HROW + kk);
                a[mt][2] = *(const uint32_t*)(sa + m*HROW + kk + 8);
                a[mt][3] = *(const uint32_t*)(sa + (m+8)*HROW + kk + 8);
            }
            #pragma unroll
            for (int nt=0;nt<8;nt++) {
                int n = wn + nt*8 + r;
                uint32_t b0 = *(const uint32_t*)(sb + n*HROW + kk);
                uint32_t b1 = *(const uint32_t*)(sb + n*HROW + kk + 8);
                mma16h(acc[0][nt], a[0][0], a[0][1], a[0][2], a[0][3], b0, b1);
                mma16h(acc[1][nt], a[1][0], a[1][1], a[1][2], a[1][3], b0, b1);
            }
        }
        __syncthreads();
    }

    #pragma unroll
    for (int mt=0;mt<2;mt++) {
        #pragma unroll
        for (int nt=0;nt<8;nt++) {
            int row = row0 + wm + mt*16 + r;
            int col = col0 + wn + nt*8 + cq*2;
            long long i0 = (long long)row*N + col, i1 = (long long)(row+8)*N + col;
            if (mode == 0) {
                *(float2*)(Cf + i0) = make_float2(acc[mt][nt][0], acc[mt][nt][1]);
                *(float2*)(Cf + i1) = make_float2(acc[mt][nt][2], acc[mt][nt][3]);
            } else if (mode == 2) {
                float2 r0 = *(const float2*)(Gf + i0);
                float2 r1 = *(const float2*)(Gf + i1);
                *(float2*)(Cf + i0) = make_float2(acc[mt][nt][0]+r0.x, acc[mt][nt][1]+r0.y);
                *(float2*)(Cf + i1) = make_float2(acc[mt][nt][2]+r1.x, acc[mt][nt][3]+r1.y);
            } else { // mode 3: rope
                float c0 = acc[mt][nt][0], c1 = acc[mt][nt][1];
                float c2 = acc[mt][nt][2], c3 = acc[mt][nt][3];
                if (col < DMODEL + KVDIM) {
                    rope_pair(row,   col, c0, c1);
                    rope_pair(row+8, col, c2, c3);
                }
                *(float2*)(Cf + i0) = make_float2(c0, c1);
                *(float2*)(Cf + i1) = make_float2(c2, c3);
            }
        }
    }
}

// fused g+u grouped GEMM: 128(M)x64(N) tile; writes Hh = silu(g)*u in fp16.
__global__ void __launch_bounds__(256,2) gugemm_kernel(
    const __half* __restrict__ A, const __half* __restrict__ Bg, const __half* __restrict__ Bu,
    __half* __restrict__ Ch, int N, int K,
    const int* __restrict__ perm, const int* __restrict__ off, long long strideB)
{
    extern __shared__ char smc[];
    int row0 = blockIdx.y * 128;
    int col0 = blockIdx.x * 64;
    if (row0 >= off[NEXP]) return;
    {
        int e = 0;
        #pragma unroll
        for (int i=1; i<NEXP; i++) if (row0 >= off[i]) e = i;
        Bg += (long long)e * strideB;
        Bu += (long long)e * strideB;
    }
    int tid = threadIdx.x, wid = tid >> 5, lane = tid & 31;
    int r = lane >> 2, cq = lane & 3;
    int wm = (wid & 3) * 32, wn = (wid >> 2) * 32;
    uint32_t sbase = smem_u32(smc);

    int j = tid & 7, rg = tid >> 3;
    const char* gA[4]; uint32_t szA[4]; const char* gB[4]; uint32_t sOf[4];
    #pragma unroll
    for (int i=0;i<4;i++) {
        int rr = rg + i*32;
        sOf[i] = (uint32_t)(rr*144 + j*16);
        int ar = row0 + rr; uint32_t sz = 16;
        int pr = perm[ar]; if (pr < 0) { ar = 0; sz = 0; } else ar = pr;
        gA[i] = (const char*)(A + (size_t)ar * K) + j*16;
        szA[i] = sz;
        gB[i] = (rr < 64) ? (const char*)(Bg + (size_t)(col0 + rr) * K) + j*16
                          : (const char*)(Bu + (size_t)(col0 + rr - 64) * K) + j*16;
    }

    float accg[2][4][4], accu[2][4][4];
    #pragma unroll
    for (int mt=0;mt<2;mt++)
        #pragma unroll
        for (int nt=0;nt<4;nt++)
            #pragma unroll
            for (int q=0;q<4;q++) { accg[mt][nt][q] = 0.f; accu[mt][nt][q] = 0.f; }

    int NC = K >> 6;

    #pragma unroll
    for (int pre=0; pre<2; pre++) {
        uint32_t st = sbase + (uint32_t)(pre * 2*HSTG_B);
        size_t ko = (size_t)pre * 128;
        #pragma unroll
        for (int i=0;i<4;i++) cp16(st + sOf[i], gA[i] + ko, szA[i]);
        #pragma unroll
        for (int i=0;i<4;i++) cp16(st + HSTG_B + sOf[i], gB[i] + ko, 16);
        asm volatile("cp.async.commit_group;" ::: "memory");
    }

    #pragma unroll 1
    for (int c = 0; c < NC; ++c) {
        if (c + 2 < NC) {
            uint32_t st = sbase + (uint32_t)(((c+2)%MG_STAGES) * 2*HSTG_B);
            size_t ko = (size_t)(c+2) * 128;
            #pragma unroll
            for (int i=0;i<4;i++) cp16(st + sOf[i], gA[i] + ko, szA[i]);
            #pragma unroll
            for (int i=0;i<4;i++) cp16(st + HSTG_B + sOf[i], gB[i] + ko, 16);
            asm volatile("cp.async.commit_group;" ::: "memory");
            asm volatile("cp.async.wait_group 2;" ::: "memory");
        } else if (c + 1 < NC) {
            asm volatile("cp.async.wait_group 1;" ::: "memory");
        } else {
            asm volatile("cp.async.wait_group 0;" ::: "memory");
        }
        __syncthreads();
        const __half* sa = (const __half*)(smc + (c%MG_STAGES)*2*HSTG_B);
        const __half* sb = (const __half*)(smc + (c%MG_STAGES)*2*HSTG_B + HSTG_B);
        #pragma unroll
        for (int ks=0; ks<4; ks++) {
            int kk = ks*16 + cq*2;
            uint32_t a[2][4];
            #pragma unroll
            for (int mt=0;mt<2;mt++) {
                int m = wm + mt*16 + r;
                a[mt][0] = *(const uint32_t*)(sa + m*HROW + kk);
                a[mt][1] = *(const uint32_t*)(sa + (m+8)*HROW + kk);
                a[mt][2] = *(const uint32_t*)(sa + m*HROW + kk + 8);
                a[mt][3] = *(const uint32_t*)(sa + (m+8)*HROW + kk + 8);
            }
            #pragma unroll
            for (int nt=0;nt<4;nt++) {
                int n = wn + nt*8 + r;
                uint32_t bg0 = *(const uint32_t*)(sb + n*HROW + kk);
                uint32_t bg1 = *(const uint32_t*)(sb + n*HROW + kk + 8);
                uint32_t bu0 = *(const uint32_t*)(sb + (n+64)*HROW + kk);
                uint32_t bu1 = *(const uint32_t*)(sb + (n+64)*HROW + kk + 8);
                mma16h(accg[0][nt], a[0][0], a[0][1], a[0][2], a[0][3], bg0, bg1);
                mma16h(accg[1][nt], a[1][0], a[1][1], a[1][2], a[1][3], bg0, bg1);
                mma16h(accu[0][nt], a[0][0], a[0][1], a[0][2], a[0][3], bu0, bu1);
                mma16h(accu[1][nt], a[1][0], a[1][1], a[1][2], a[1][3], bu0, bu1);
            }
        }
        __syncthreads();
    }

    #pragma unroll
    for (int mt=0;mt<2;mt++) {
        #pragma unroll
        for (int nt=0;nt<4;nt++) {
            int row = row0 + wm + mt*16 + r;
            int col = col0 + wn + nt*8 + cq*2;
            *(__half2*)(Ch + (long long)row*N + col) = __floats2half2_rn(
                silu(accg[mt][nt][0])*accu[mt][nt][0], silu(accg[mt][nt][1])*accu[mt][nt][1]);
            *(__half2*)(Ch + (long long)(row+8)*N + col) = __floats2half2_rn(
                silu(accg[mt][nt][2])*accu[mt][nt][2], silu(accg[mt][nt][3])*accu[mt][nt][3]);
        }
    }
}

// flash attention, scalar per-key loop (proven R12 config) + unroll-2 for cross-key ILP
__global__ __launch_bounds__(64) void attn_kernel(
    const float* __restrict__ QKV, __half* __restrict__ Os)
{
    __shared__ float Ks[64][64];
    __shared__ float Vs[64][64];
    int tid = threadIdx.x;
    int q0 = blockIdx.x * 64;
    int h  = blockIdx.y;
    int b  = blockIdx.z;
    int kvh = h >> 2;
    int qi = q0 + tid;
    long long t = (long long)b*SEQ + qi;
    float q[HD], o[HD];
    const float4* qp = (const float4*)(QKV + t*QKVN + h*HD);
    #pragma unroll
    for (int i=0;i<16;i++) {
        float4 f = qp[i];
        q[4*i]=f.x*0.125f; q[4*i+1]=f.y*0.125f; q[4*i+2]=f.z*0.125f; q[4*i+3]=f.w*0.125f;
    }
    #pragma unroll
    for (int d=0; d<HD; d++) o[d] = 0.f;
    float m = -1e30f, l = 0.f;
    int ntiles = q0/64 + 1;
    for (int kt=0; kt<ntiles; kt++) {
        for (int idx=tid; idx<64*16; idx+=64) {
            int rr = idx >> 4, cc = idx & 15;
            long long base = ((long long)(b*SEQ + kt*64 + rr))*QKVN + DMODEL + kvh*HD + cc*4;
            *(float4*)&Ks[rr][cc*4] = *(const float4*)(QKV + base);
            *(float4*)&Vs[rr][cc*4] = *(const float4*)(QKV + base + KVDIM);
        }
        __syncthreads();
        int jend = min(64, qi - kt*64 + 1);
        #pragma unroll 2
        for (int jj=0; jj<jend; jj++) {
            float s0=0.f,s1=0.f,s2=0.f,s3=0.f;
            const float4* kr = (const float4*)&Ks[jj][0];
            #pragma unroll
            for (int i=0;i<16;i++) {
                float4 kv4 = kr[i];
                s0 += q[4*i]*kv4.x; s1 += q[4*i+1]*kv4.y;
                s2 += q[4*i+2]*kv4.z; s3 += q[4*i+3]*kv4.w;
            }
            float s = (s0+s1)+(s2+s3);
            if (s > m) {
                float corr = __expf(m - s);
                l *= corr;
                #pragma unroll
                for (int d=0; d<HD; d++) o[d] *= corr;
                m = s;
            }
            float p = __expf(s - m);
            l += p;
            const float4* vr = (const float4*)&Vs[jj][0];
            #pragma unroll
            for (int i=0;i<16;i++) {
                float4 vv = vr[i];
                o[4*i] += p*vv.x; o[4*i+1] += p*vv.y;
                o[4*i+2] += p*vv.z; o[4*i+3] += p*vv.w;
            }
        }
        __syncthreads();
    }
    float inv = 1.f / l;
    __half2* d = (__half2*)(Os + (size_t)t*K3);
    #pragma unroll
    for (int i=0;i<16;i++) {
        int c = h*HD + 4*i;
        float vx = o[4*i]*inv, vy = o[4*i+1]*inv, vz = o[4*i+2]*inv, vw = o[4*i+3]*inv;
        __half2 h0,l0,h1,l1;
        split2(vx, vy, h0, l0);
        split2(vz, vw, h1, l1);
        d[c/2] = h0;              d[c/2+1] = h1;
        d[(DMODEL+c)/2] = l0;     d[(DMODEL+c)/2+1] = l1;
        d[(2*DMODEL+c)/2] = h0;   d[(2*DMODEL+c)/2+1] = h1;
    }
}

__global__ void router_kernel(const float* __restrict__ XN, const float* __restrict__ RW) {
    __shared__ float sw[NEXP*DMODEL];
    int tid = threadIdx.x;
    for (int i=tid; i<NEXP*DMODEL/4; i+=256)
        ((float4*)sw)[i] = ((const float4*)RW)[i];
    __syncthreads();
    int warp = tid >> 5, lane = tid & 31;
    int token = blockIdx.x*8 + warp;
    const float* xr = XN + (long long)token*DMODEL;
    float acc[NEXP];
    #pragma unroll
    for (int e=0;e<NEXP;e++) acc[e]=0.f;
    for (int d=lane; d<DMODEL; d+=32) {
        float xv = xr[d];
        #pragma unroll
        for (int e=0;e<NEXP;e++) acc[e] += xv * sw[e*DMODEL + d];
    }
    #pragma unroll
    for (int e=0;e<NEXP;e++)
        #pragma unroll
        for (int off=16; off; off>>=1) acc[e] += __shfl_xor_sync(0xffffffffu, acc[e], off);
    if (lane == 0) {
        float mx = acc[0];
        #pragma unroll
        for (int e=1;e<NEXP;e++) mx = fmaxf(mx, acc[e]);
        float pe[NEXP], sum = 0.f;
        #pragma unroll
        for (int e=0;e<NEXP;e++) { pe[e] = expf(acc[e]-mx); sum += pe[e]; }
        float inv = 1.f/sum;
        #pragma unroll
        for (int e=0;e<NEXP;e++) { pe[e] *= inv; g_probs_all[token*NEXP+e] = pe[e]; }
        int e1 = 0; float p1 = pe[0];
        #pragma unroll
        for (int e=1;e<NEXP;e++) if (pe[e] > p1) { p1 = pe[e]; e1 = e; }
        int e2 = -1; float p2 = -1.f;
        #pragma unroll
        for (int e=0;e<NEXP;e++) if (e != e1 && pe[e] > p2) { p2 = pe[e]; e2 = e; }
        float rn = 1.f/(p1+p2);
        g_topk_e[token*2]   = e1;  g_topk_e[token*2+1] = e2;
        g_topk_p[token*2]   = p1*rn; g_topk_p[token*2+1] = p2*rn;
        atomicAdd(&g_cnt[e1], 1);
        atomicAdd(&g_cnt[e2], 1);
    }
}

__global__ void psum_kernel() {
    int e = blockIdx.x;
    int tid = threadIdx.x;
    float acc = 0.f;
    for (int t=tid; t<NTOK; t+=256) acc += g_probs_all[t*NEXP + e];
    #pragma unroll
    for (int off=16; off; off>>=1) acc += __shfl_xor_sync(0xffffffffu, acc, off);
    __shared__ float red[8];
    if ((tid & 31) == 0) red[tid>>5] = acc;
    __syncthreads();
    if (tid < 8) {
        float v = red[tid];
        #pragma unroll
        for (int off=4; off; off>>=1) v += __shfl_xor_sync(0xffu, v, off);
        if (tid == 0) g_Psum[e] = v;
    }
}

__global__ void finalize_kernel(float* __restrict__ out, int out_size) {
    if (threadIdx.x == 0 && blockIdx.x == 0) {
        int total = 0;
        for (int e=0; e<NEXP; e++) {
            g_off[e] = total; g_cur[e] = total;
            total += ((g_cnt[e] + 127)/128)*128;
        }
        g_off[NEXP] = total;
        float aux = 0.f;
        for (int e=0; e<NEXP; e++)
            aux += ((float)g_cnt[e] / (float)NSLOT) * (g_Psum[e] / (float)NTOK);
        out[out_size-9] = (float)NEXP * aux;
        for (int e=0; e<NEXP; e++) out[out_size-8+e] = (float)g_cnt[e];
    }
}

__global__ void assign_kernel() {
    int token = blockIdx.x*256 + threadIdx.x;
    if (token >= NTOK) return;
    #pragma unroll
    for (int kk=0; kk<TOPK; kk++) {
        int e = g_topk_e[token*2+kk];
        int pos = atomicAdd(&g_cur[e], 1);
        g_perm[pos] = token;
        g_prob[pos] = g_topk_p[token*2+kk];
        g_posOf[token*2+kk] = pos;
    }
}

__global__ void combine_kernel(float* __restrict__ out) {
    int t = blockIdx.x;
    int tid = threadIdx.x;
    int p1i = g_posOf[t*2], p2i = g_posOf[t*2+1];
    float p1 = g_prob[p1i], p2 = g_prob[p2i];
    float4 a  = ((const float4*)(g_x1 + (long long)t*DMODEL))[tid];
    float4 y1 = ((const float4*)(g_Y  + (long long)p1i*DMODEL))[tid];
    float4 y2 = ((const float4*)(g_Y  + (long long)p2i*DMODEL))[tid];
    ((float4*)(out + (long long)t*DMODEL))[tid] = make_float4(
        a.x + p1*y1.x + p2*y2.x, a.y + p1*y1.y + p2*y2.y,
        a.z + p1*y1.z + p2*y2.z, a.w + p1*y1.w + p2*y2.w);
}

extern "C" void kernel_launch(void* const* d_in, const int* in_sizes, int n_in,
                              void* d_out, int out_size) {
    const float* x        = (const float*)d_in[0];
    const float* wq       = (const float*)d_in[1];
    const float* wk       = (const float*)d_in[2];
    const float* wv       = (const float*)d_in[3];
    const float* wo       = (const float*)d_in[4];
    const float* attn_nw  = (const float*)d_in[5];
    const float* ffn_nw   = (const float*)d_in[6];
    const float* router_w = (const float*)d_in[7];
    const float* Wg       = (const float*)d_in[8];
    const float* Wu       = (const float*)d_in[9];
    const float* Wd       = (const float*)d_in[10];
    float* out = (float*)d_out;

    float *p_xn,*p_qkv,*p_x1,*p_Y;
    __half *p_xns,*p_xnt,*p_attns,*p_Wqkvs,*p_Wos,*p_Hh,*p_Wgt,*p_Wut,*p_Wdt;
    int *p_perm, *p_off;
    cudaGetSymbolAddress((void**)&p_xn,   g_xn);
    cudaGetSymbolAddress((void**)&p_xns,  g_xns);
    cudaGetSymbolAddress((void**)&p_xnt,  g_xnt);
    cudaGetSymbolAddress((void**)&p_qkv,  g_qkv);
    cudaGetSymbolAddress((void**)&p_attns,g_attns);
    cudaGetSymbolAddress((void**)&p_x1,   g_x1);
    cudaGetSymbolAddress((void**)&p_Hh,   g_Hh);
    cudaGetSymbolAddress((void**)&p_Y,    g_Y);
    cudaGetSymbolAddress((void**)&p_Wqkvs,g_Wqkvs);
    cudaGetSymbolAddress((void**)&p_Wos,  g_Wos);
    cudaGetSymbolAddress((void**)&p_Wgt,  g_Wgt);
    cudaGetSymbolAddress((void**)&p_Wut,  g_Wut);
    cudaGetSymbolAddress((void**)&p_Wdt,  g_Wdt);
    cudaGetSymbolAddress((void**)&p_perm, g_perm);
    cudaGetSymbolAddress((void**)&p_off,  g_off);

    cudaFuncSetAttribute(mgemm_kernel, cudaFuncAttributeMaxDynamicSharedMemorySize, MG_SMEM);
    cudaFuncSetAttribute(gugemm_kernel, cudaFuncAttributeMaxDynamicSharedMemorySize, MG_SMEM);

    // attn_kernel stays at launch index 3 (ncu profiles idx 3)
    rmsnorm_kernel<<<NTOK, 256>>>(x, attn_nw, nullptr, nullptr, p_xns);            // 0
    cvtsplit3_kernel<<<(NWQ+2*NWK+255)/256, 256>>>(
        (const float4*)wq, (const float4*)wk, (const float4*)wv, p_Wqkvs);         // 1
    mgemm_kernel<<<dim3(QKVN/128, NTOK/128), 256, MG_SMEM>>>(
        p_xns, p_Wqkvs, p_qkv, nullptr, QKVN, K3, nullptr, nullptr, 0, 3);         // 2 (qkv + fused rope)
    attn_kernel<<<dim3(SEQ/64, NHEADS, BATCH), 64>>>(p_qkv, p_attns);              // 3 <- profiled

    init_kernel<<<(NSLOT_PAD+255)/256, 256>>>();

    cvtsplit_kernel<<<(DMODEL*DMODEL/4+255)/256, 256>>>((const float4*)wo, p_Wos, DMODEL, DMODEL*DMODEL/4);

    mgemm_kernel<<<dim3(DMODEL/128, NTOK/128), 256, MG_SMEM>>>(
        p_attns, p_Wos, p_x1, x, DMODEL, K3, nullptr, nullptr, 0, 2);

    rmsnorm_kernel<<<NTOK, 256>>>(p_x1, ffn_nw, p_xn, p_xnt, nullptr);

    router_kernel<<<NTOK/8, 256>>>(p_xn, router_w);
    psum_kernel<<<NEXP, 256>>>();
    finalize_kernel<<<1, 32>>>(out, out_size);
    assign_kernel<<<NTOK/256, 256>>>();

    const int nW = NEXP*DFF*DMODEL/4;
    cvth_kernel<<<(nW+255)/256, 256>>>((const float4*)Wg, (__half2*)p_Wgt, nW);
    cvth_kernel<<<(nW+255)/256, 256>>>((const float4*)Wu, (__half2*)p_Wut, nW);
    cvth_kernel<<<(nW+255)/256, 256>>>((const float4*)Wd, (__half2*)p_Wdt, nW);

    gugemm_kernel<<<dim3(DFF/64, NSLOT_PAD/128), 256, MG_SMEM>>>(
        p_xnt, p_Wgt, p_Wut, p_Hh, DFF, DMODEL, p_perm, p_off, (long long)DFF*DMODEL);
    mgemm_kernel<<<dim3(DMODEL/128, NSLOT_PAD/128), 256, MG_SMEM>>>(
        p_Hh, p_Wdt, p_Y, nullptr, DMODEL, DFF, nullptr, p_off, (long long)DMODEL*DFF, 0);

    combine_kernel<<<NTOK, 256>>>(out);
}

// round 16
// speedup vs baseline: 1.2466x; 1.0021x over previous
#include <cuda_runtime.h>
#include <cuda_fp16.h>
#include <math.h>
#include <stdint.h>

#define BATCH 2
#define SEQ 2048
#define NTOK (BATCH*SEQ)
#define DMODEL 1024
#define DFF 2048
#define NHEADS 16
#define NKVHEADS 4
#define HD 64
#define KVDIM (NKVHEADS*HD)
#define QKVN (DMODEL+2*KVDIM)   // 1536
#define K3 (3*DMODEL)           // 3072 split-K
#define NEXP 8
#define TOPK 2
#define NSLOT (NTOK*TOPK)
#define NSLOT_PAD 9216

__device__ float  g_xn[NTOK*DMODEL];
__device__ __half g_xns[NTOK*K3];
__device__ __half g_xnt[NTOK*DMODEL];
__device__ float  g_qkv[NTOK*QKVN];
__device__ __half g_attns[NTOK*K3];
__device__ float  g_x1[NTOK*DMODEL];
__device__ __half g_Hh[NSLOT_PAD*DFF];
__device__ float  g_Y[NSLOT_PAD*DMODEL];
__device__ __half g_Wqkvs[QKVN*K3];
__device__ __half g_Wos[DMODEL*K3];
__device__ __half g_Wgt[NEXP*DFF*DMODEL];
__device__ __half g_Wut[NEXP*DFF*DMODEL];
__device__ __half g_Wdt[NEXP*DMODEL*DFF];
__device__ int    g_perm[NSLOT_PAD];
__device__ float  g_prob[NSLOT_PAD];
__device__ int    g_posOf[NTOK*TOPK];
__device__ int    g_topk_e[NTOK*TOPK];
__device__ float  g_topk_p[NTOK*TOPK];
__device__ float  g_probs_all[NTOK*NEXP];
__device__ int    g_cnt[NEXP];
__device__ int    g_off[NEXP+1];
__device__ int    g_cur[NEXP];
__device__ float  g_Psum[NEXP];

__device__ __forceinline__ void cp16(uint32_t dst, const void* src, uint32_t sz) {
    asm volatile("cp.async.cg.shared.global [%0], [%1], 16, %2;" :: "r"(dst), "l"(src), "r"(sz) : "memory");
}
__device__ __forceinline__ uint32_t smem_u32(const void* p) {
    uint32_t a;
    asm("{ .reg .u64 t; cvta.to.shared.u64 t, %1; cvt.u32.u64 %0, t; }" : "=r"(a) : "l"(p));
    return a;
}
__device__ __forceinline__ void mma16h(float* c, uint32_t a0, uint32_t a1, uint32_t a2,
                                       uint32_t a3, uint32_t b0, uint32_t b1) {
    asm volatile("mma.sync.aligned.m16n8k16.row.col.f32.f16.f16.f32 "
        "{%0,%1,%2,%3}, {%4,%5,%6,%7}, {%8,%9}, {%0,%1,%2,%3};"
        : "+f"(c[0]), "+f"(c[1]), "+f"(c[2]), "+f"(c[3])
        : "r"(a0), "r"(a1), "r"(a2), "r"(a3), "r"(b0), "r"(b1));
}
__device__ __forceinline__ float silu(float g) { return g / (1.f + __expf(-g)); }
__device__ __forceinline__ void split2(float x, float y, __half2& h, __half2& l) {
    __half hx = __float2half_rn(x), hy = __float2half_rn(y);
    h = __halves2half2(hx, hy);
    l = __floats2half2_rn(x - __half2float(hx), y - __half2float(hy));
}

__global__ void init_kernel() {
    int i = blockIdx.x*256 + threadIdx.x;
    if (i < NSLOT_PAD) g_perm[i] = -1;
    if (i < NEXP) { g_cnt[i] = 0; g_Psum[i] = 0.f; }
}

// merged 3-weight fp32->fp16 convert (Wg, Wu, Wd)
#define NW4 (NEXP*DFF*DMODEL/4)
__global__ void cvth3_kernel(const float4* __restrict__ s0, const float4* __restrict__ s1,
                             const float4* __restrict__ s2, __half2* __restrict__ d0,
                             __half2* __restrict__ d1, __half2* __restrict__ d2) {
    int i = blockIdx.x*256 + threadIdx.x;
    const float4* s; __half2* d; int k;
    if (i < NW4)            { s = s0; d = d0; k = i; }
    else if (i < 2*NW4)     { s = s1; d = d1; k = i - NW4; }
    else if (i < 3*NW4)     { s = s2; d = d2; k = i - 2*NW4; }
    else return;
    float4 v = s[k];
    d[2*k]   = __floats2half2_rn(v.x, v.y);
    d[2*k+1] = __floats2half2_rn(v.z, v.w);
}

__device__ __forceinline__ void cvtsplit_one(const float4* src, __half* dst, int K, int i) {
    int kq = K >> 2;
    int n = i / kq, c = (i - n*kq) * 4;
    float4 v = src[i];
    __half2 h0, l0, h1, l1;
    split2(v.x, v.y, h0, l0);
    split2(v.z, v.w, h1, l1);
    __half2* d = (__half2*)(dst + (size_t)n*3*K);
    d[c/2] = h0;         d[c/2+1] = h1;
    d[(K+c)/2] = h0;     d[(K+c)/2+1] = h1;
    d[(2*K+c)/2] = l0;   d[(2*K+c)/2+1] = l1;
}

__global__ void cvtsplit_kernel(const float4* __restrict__ src, __half* __restrict__ dst,
                                int K, int n4) {
    int i = blockIdx.x*256 + threadIdx.x;
    if (i < n4) cvtsplit_one(src, dst, K, i);
}

#define NWQ (DMODEL*DMODEL/4)
#define NWK (KVDIM*DMODEL/4)
__global__ void cvtsplit3_kernel(const float4* __restrict__ wq, const float4* __restrict__ wk,
                                 const float4* __restrict__ wv, __half* __restrict__ dst) {
    int i = blockIdx.x*256 + threadIdx.x;
    if (i < NWQ) {
        cvtsplit_one(wq, dst, DMODEL, i);
    } else if (i < NWQ + NWK) {
        cvtsplit_one(wk, dst + (size_t)DMODEL*K3, DMODEL, i - NWQ);
    } else if (i < NWQ + 2*NWK) {
        cvtsplit_one(wv, dst + (size_t)(DMODEL+KVDIM)*K3, DMODEL, i - NWQ - NWK);
    }
}

__global__ void rmsnorm_kernel(const float* __restrict__ X, const float* __restrict__ W,
                               float* __restrict__ Y, __half* __restrict__ Yt,
                               __half* __restrict__ Ys) {
    int t = blockIdx.x;
    int tid = threadIdx.x;
    float4 xv = ((const float4*)(X + (long long)t*DMODEL))[tid];
    float ss = xv.x*xv.x + xv.y*xv.y + xv.z*xv.z + xv.w*xv.w;
    #pragma unroll
    for (int off=16; off; off>>=1) ss += __shfl_xor_sync(0xffffffffu, ss, off);
    __shared__ float red[8];
    if ((tid & 31) == 0) red[tid>>5] = ss;
    __syncthreads();
    if (tid < 8) {
        float v = red[tid];
        #pragma unroll
        for (int off=4; off; off>>=1) v += __shfl_xor_sync(0xffu, v, off);
        if (tid == 0) red[0] = v;
    }
    __syncthreads();
    float r = rsqrtf(red[0]/(float)DMODEL + 1e-6f);
    float4 wv = ((const float4*)W)[tid];
    float4 o = make_float4(xv.x*r*wv.x, xv.y*r*wv.y, xv.z*r*wv.z, xv.w*r*wv.w);
    if (Y) ((float4*)(Y + (long long)t*DMODEL))[tid] = o;
    if (Yt) {
        __half2* yh = (__half2*)(Yt + (long long)t*DMODEL);
        yh[2*tid]   = __floats2half2_rn(o.x, o.y);
        yh[2*tid+1] = __floats2half2_rn(o.z, o.w);
    }
    if (Ys) {
        int c = 4*tid;
        __half2 h0,l0,h1,l1;
        split2(o.x, o.y, h0, l0);
        split2(o.z, o.w, h1, l1);
        __half2* d = (__half2*)(Ys + (size_t)t*K3);
        d[c/2] = h0;              d[c/2+1] = h1;
        d[(DMODEL+c)/2] = l0;     d[(DMODEL+c)/2+1] = l1;
        d[(2*DMODEL+c)/2] = h0;   d[(2*DMODEL+c)/2+1] = h1;
    }
}

__device__ __forceinline__ void rope_pair(int row, int col, float& c0, float& c1) {
    int s = row & (SEQ-1);
    int elem = col & 63;
    float f = (float)(elem & 31);
    float freq = powf(10000.f, -f/32.f);
    float ang = (float)s * freq;
    float cc = cosf(ang), sn = sinf(ang);
    float x1 = c0, x2 = c1;
    c0 = x1*cc - x2*sn;
    c1 = x1*sn + x2*cc;
}

// fp16 mma GEMM: acc[M,N] = A[M,K]@B[N,K]^T (fp32 accum), 128x128x64, 3-stage, m16n8k16.
// modes: 0 Cf=acc; 2 Cf=acc+Gf (residual); 3 Cf=rope(acc) (qkv epilogue)
#define HROW 72
#define HSTG_B (128*144)
#define MG_STAGES 3
#define MG_SMEM (MG_STAGES*2*HSTG_B)
__global__ void __launch_bounds__(256,2) mgemm_kernel(
    const __half* __restrict__ A, const __half* __restrict__ B,
    float* __restrict__ Cf, const float* __restrict__ Gf,
    int N, int K, const int* __restrict__ perm, const int* __restrict__ off,
    long long strideB, int mode)
{
    extern __shared__ char smc[];
    int row0 = blockIdx.y * 128;
    int col0 = blockIdx.x * 128;
    if (off) {
        if (row0 >= off[NEXP]) return;
        int e = 0;
        #pragma unroll
        for (int i=1; i<NEXP; i++) if (row0 >= off[i]) e = i;
        B += (long long)e * strideB;
    }
    int tid = threadIdx.x, wid = tid >> 5, lane = tid & 31;
    int r = lane >> 2, cq = lane & 3;
    int wm = (wid & 3) * 32, wn = (wid >> 2) * 64;
    uint32_t sbase = smem_u32(smc);

    int j = tid & 7, rg = tid >> 3;
    const char* gA[4]; uint32_t szA[4]; const char* gB[4]; uint32_t sOf[4];
    #pragma unroll
    for (int i=0;i<4;i++) {
        int rr = rg + i*32;
        sOf[i] = (uint32_t)(rr*144 + j*16);
        int ar = row0 + rr; uint32_t sz = 16;
        if (perm) { int pr = perm[ar]; if (pr < 0) { ar = 0; sz = 0; } else ar = pr; }
        gA[i] = (const char*)(A + (size_t)ar * K) + j*16;
        szA[i] = sz;
        gB[i] = (const char*)(B + (size_t)(col0 + rr) * K) + j*16;
    }

    float acc[2][8][4];
    #pragma unroll
    for (int mt=0;mt<2;mt++)
        #pragma unroll
        for (int nt=0;nt<8;nt++)
            #pragma unroll
            for (int q=0;q<4;q++) acc[mt][nt][q] = 0.f;

    int NC = K >> 6;

    #pragma unroll
    for (int pre=0; pre<2; pre++) {
        uint32_t st = sbase + (uint32_t)(pre * 2*HSTG_B);
        size_t ko = (size_t)pre * 128;
        #pragma unroll
        for (int i=0;i<4;i++) cp16(st + sOf[i], gA[i] + ko, szA[i]);
        #pragma unroll
        for (int i=0;i<4;i++) cp16(st + HSTG_B + sOf[i], gB[i] + ko, 16);
        asm volatile("cp.async.commit_group;" ::: "memory");
    }

    #pragma unroll 1
    for (int c = 0; c < NC; ++c) {
        if (c + 2 < NC) {
            uint32_t st = sbase + (uint32_t)(((c+2)%MG_STAGES) * 2*HSTG_B);
            size_t ko = (size_t)(c+2) * 128;
            #pragma unroll
            for (int i=0;i<4;i++) cp16(st + sOf[i], gA[i] + ko, szA[i]);
            #pragma unroll
            for (int i=0;i<4;i++) cp16(st + HSTG_B + sOf[i], gB[i] + ko, 16);
            asm volatile("cp.async.commit_group;" ::: "memory");
            asm volatile("cp.async.wait_group 2;" ::: "memory");
        } else if (c + 1 < NC) {
            asm volatile("cp.async.wait_group 1;" ::: "memory");
        } else {
            asm volatile("cp.async.wait_group 0;" ::: "memory");
        }
        __syncthreads();
        const __half* sa = (const __half*)(smc + (c%MG_STAGES)*2*HSTG_B);
        const __half* sb = (const __half*)(smc + (c%MG_STAGES)*2*HSTG_B + HSTG_B);
        #pragma unroll
        for (int ks=0; ks<4; ks++) {
            int kk = ks*16 + cq*2;
            uint32_t a[2][4];
            #pragma unroll
            for (int mt=0;mt<2;mt++) {
                int m = wm + mt*16 + r;
                a[mt][0] = *(const uint32_t*)(sa + m*HROW + kk);
                a[mt][1] = *(const uint32_t*)(sa + (m+8)*HROW + kk);
                a[mt][2] = *(const uint32_t*)(sa + m*HROW + kk + 8);
                a[mt][3] = *(const uint32_t*)(sa + (m+8)*HROW + kk + 8);
            }
            #pragma unroll
            for (int nt=0;nt<8;nt++) {
                int n = wn + nt*8 + r;
                uint32_t b0 = *(const uint32_t*)(sb + n*HROW + kk);
                uint32_t b1 = *(const uint32_t*)(sb + n*HROW + kk + 8);
                mma16h(acc[0][nt], a[0][0], a[0][1], a[0][2], a[0][3], b0, b1);
                mma16h(acc[1][nt], a[1][0], a[1][1], a[1][2], a[1][3], b0, b1);
            }
        }
        __syncthreads();
    }

    #pragma unroll
    for (int mt=0;mt<2;mt++) {
        #pragma unroll
        for (int nt=0;nt<8;nt++) {
            int row = row0 + wm + mt*16 + r;
            int col = col0 + wn + nt*8 + cq*2;
            long long i0 = (long long)row*N + col, i1 = (long long)(row+8)*N + col;
            if (mode == 0) {
                *(float2*)(Cf + i0) = make_float2(acc[mt][nt][0], acc[mt][nt][1]);
                *(float2*)(Cf + i1) = make_float2(acc[mt][nt][2], acc[mt][nt][3]);
            } else if (mode == 2) {
                float2 r0 = *(const float2*)(Gf + i0);
                float2 r1 = *(const float2*)(Gf + i1);
                *(float2*)(Cf + i0) = make_float2(acc[mt][nt][0]+r0.x, acc[mt][nt][1]+r0.y);
                *(float2*)(Cf + i1) = make_float2(acc[mt][nt][2]+r1.x, acc[mt][nt][3]+r1.y);
            } else { // mode 3: rope
                float c0 = acc[mt][nt][0], c1 = acc[mt][nt][1];
                float c2 = acc[mt][nt][2], c3 = acc[mt][nt][3];
                if (col < DMODEL + KVDIM) {
                    rope_pair(row,   col, c0, c1);
                    rope_pair(row+8, col, c2, c3);
                }
                *(float2*)(Cf + i0) = make_float2(c0, c1);
                *(float2*)(Cf + i1) = make_float2(c2, c3);
            }
        }
    }
}

// fused g+u grouped GEMM: 128(M)x64(N) tile; writes Hh = silu(g)*u in fp16.
__global__ void __launch_bounds__(256,2) gugemm_kernel(
    const __half* __restrict__ A, const __half* __restrict__ Bg, const __half* __restrict__ Bu,
    __half* __restrict__ Ch, int N, int K,
    const int* __restrict__ perm, const int* __restrict__ off, long long strideB)
{
    extern __shared__ char smc[];
    int row0 = blockIdx.y * 128;
    int col0 = blockIdx.x * 64;
    if (row0 >= off[NEXP]) return;
    {
        int e = 0;
        #pragma unroll
        for (int i=1; i<NEXP; i++) if (row0 >= off[i]) e = i;
        Bg += (long long)e * strideB;
        Bu += (long long)e * strideB;
    }
    int tid = threadIdx.x, wid = tid >> 5, lane = tid & 31;
    int r = lane >> 2, cq = lane & 3;
    int wm = (wid & 3) * 32, wn = (wid >> 2) * 32;
    uint32_t sbase = smem_u32(smc);

    int j = tid & 7, rg = tid >> 3;
    const char* gA[4]; uint32_t szA[4]; const char* gB[4]; uint32_t sOf[4];
    #pragma unroll
    for (int i=0;i<4;i++) {
        int rr = rg + i*32;
        sOf[i] = (uint32_t)(rr*144 + j*16);
        int ar = row0 + rr; uint32_t sz = 16;
        int pr = perm[ar]; if (pr < 0) { ar = 0; sz = 0; } else ar = pr;
        gA[i] = (const char*)(A + (size_t)ar * K) + j*16;
        szA[i] = sz;
        gB[i] = (rr < 64) ? (const char*)(Bg + (size_t)(col0 + rr) * K) + j*16
                          : (const char*)(Bu + (size_t)(col0 + rr - 64) * K) + j*16;
    }

    float accg[2][4][4], accu[2][4][4];
    #pragma unroll
    for (int mt=0;mt<2;mt++)
        #pragma unroll
        for (int nt=0;nt<4;nt++)
            #pragma unroll
            for (int q=0;q<4;q++) { accg[mt][nt][q] = 0.f; accu[mt][nt][q] = 0.f; }

    int NC = K >> 6;

    #pragma unroll
    for (int pre=0; pre<2; pre++) {
        uint32_t st = sbase + (uint32_t)(pre * 2*HSTG_B);
        size_t ko = (size_t)pre * 128;
        #pragma unroll
        for (int i=0;i<4;i++) cp16(st + sOf[i], gA[i] + ko, szA[i]);
        #pragma unroll
        for (int i=0;i<4;i++) cp16(st + HSTG_B + sOf[i], gB[i] + ko, 16);
        asm volatile("cp.async.commit_group;" ::: "memory");
    }

    #pragma unroll 1
    for (int c = 0; c < NC; ++c) {
        if (c + 2 < NC) {
            uint32_t st = sbase + (uint32_t)(((c+2)%MG_STAGES) * 2*HSTG_B);
            size_t ko = (size_t)(c+2) * 128;
            #pragma unroll
            for (int i=0;i<4;i++) cp16(st + sOf[i], gA[i] + ko, szA[i]);
            #pragma unroll
            for (int i=0;i<4;i++) cp16(st + HSTG_B + sOf[i], gB[i] + ko, 16);
            asm volatile("cp.async.commit_group;" ::: "memory");
            asm volatile("cp.async.wait_group 2;" ::: "memory");
        } else if (c + 1 < NC) {
            asm volatile("cp.async.wait_group 1;" ::: "memory");
        } else {
            asm volatile("cp.async.wait_group 0;" ::: "memory");
        }
        __syncthreads();
        const __half* sa = (const __half*)(smc + (c%MG_STAGES)*2*HSTG_B);
        const __half* sb = (const __half*)(smc + (c%MG_STAGES)*2*HSTG_B + HSTG_B);
        #pragma unroll
        for (int ks=0; ks<4; ks++) {
            int kk = ks*16 + cq*2;
            uint32_t a[2][4];
            #pragma unroll
            for (int mt=0;mt<2;mt++) {
                int m = wm + mt*16 + r;
                a[mt][0] = *(const uint32_t*)(sa + m*HROW + kk);
                a[mt][1] = *(const uint32_t*)(sa + (m+8)*HROW + kk);
                a[mt][2] = *(const uint32_t*)(sa + m*HROW + kk + 8);
                a[mt][3] = *(const uint32_t*)(sa + (m+8)*HROW + kk + 8);
            }
            #pragma unroll
            for (int nt=0;nt<4;nt++) {
                int n = wn + nt*8 + r;
                uint32_t bg0 = *(const uint32_t*)(sb + n*HROW + kk);
                uint32_t bg1 = *(const uint32_t*)(sb + n*HROW + kk + 8);
                uint32_t bu0 = *(const uint32_t*)(sb + (n+64)*HROW + kk);
                uint32_t bu1 = *(const uint32_t*)(sb + (n+64)*HROW + kk + 8);
                mma16h(accg[0][nt], a[0][0], a[0][1], a[0][2], a[0][3], bg0, bg1);
                mma16h(accg[1][nt], a[1][0], a[1][1], a[1][2], a[1][3], bg0, bg1);
                mma16h(accu[0][nt], a[0][0], a[0][1], a[0][2], a[0][3], bu0, bu1);
                mma16h(accu[1][nt], a[1][0], a[1][1], a[1][2], a[1][3], bu0, bu1);
            }
        }
        __syncthreads();
    }

    #pragma unroll
    for (int mt=0;mt<2;mt++) {
        #pragma unroll
        for (int nt=0;nt<4;nt++) {
            int row = row0 + wm + mt*16 + r;
            int col = col0 + wn + nt*8 + cq*2;
            *(__half2*)(Ch + (long long)row*N + col) = __floats2half2_rn(
                silu(accg[mt][nt][0])*accu[mt][nt][0], silu(accg[mt][nt][1])*accu[mt][nt][1]);
            *(__half2*)(Ch + (long long)(row+8)*N + col) = __floats2half2_rn(
                silu(accg[mt][nt][2])*accu[mt][nt][2], silu(accg[mt][nt][3])*accu[mt][nt][3]);
        }
    }
}

// flash attention, scalar per-key loop + unroll-2; longest q-tiles launch first (LPT)
__global__ __launch_bounds__(64) void attn_kernel(
    const float* __restrict__ QKV, __half* __restrict__ Os)
{
    __shared__ float Ks[64][64];
    __shared__ float Vs[64][64];
    int tid = threadIdx.x;
    int q0 = (gridDim.x - 1 - blockIdx.x) * 64;   // reversed: long blocks first
    int h  = blockIdx.y;
    int b  = blockIdx.z;
    int kvh = h >> 2;
    int qi = q0 + tid;
    long long t = (long long)b*SEQ + qi;
    float q[HD], o[HD];
    const float4* qp = (const float4*)(QKV + t*QKVN + h*HD);
    #pragma unroll
    for (int i=0;i<16;i++) {
        float4 f = qp[i];
        q[4*i]=f.x*0.125f; q[4*i+1]=f.y*0.125f; q[4*i+2]=f.z*0.125f; q[4*i+3]=f.w*0.125f;
    }
    #pragma unroll
    for (int d=0; d<HD; d++) o[d] = 0.f;
    float m = -1e30f, l = 0.f;
    int ntiles = q0/64 + 1;
    for (int kt=0; kt<ntiles; kt++) {
        for (int idx=tid; idx<64*16; idx+=64) {
            int rr = idx >> 4, cc = idx & 15;
            long long base = ((long long)(b*SEQ + kt*64 + rr))*QKVN + DMODEL + kvh*HD + cc*4;
            *(float4*)&Ks[rr][cc*4] = *(const float4*)(QKV + base);
            *(float4*)&Vs[rr][cc*4] = *(const float4*)(QKV + base + KVDIM);
        }
        __syncthreads();
        int jend = min(64, qi - kt*64 + 1);
        #pragma unroll 2
        for (int jj=0; jj<jend; jj++) {
            float s0=0.f,s1=0.f,s2=0.f,s3=0.f;
            const float4* kr = (const float4*)&Ks[jj][0];
            #pragma unroll
            for (int i=0;i<16;i++) {
                float4 kv4 = kr[i];
                s0 += q[4*i]*kv4.x; s1 += q[4*i+1]*kv4.y;
                s2 += q[4*i+2]*kv4.z; s3 += q[4*i+3]*kv4.w;
            }
            float s = (s0+s1)+(s2+s3);
            if (s > m) {
                float corr = __expf(m - s);
                l *= corr;
                #pragma unroll
                for (int d=0; d<HD; d++) o[d] *= corr;
                m = s;
            }
            float p = __expf(s - m);
            l += p;
            const float4* vr = (const float4*)&Vs[jj][0];
            #pragma unroll
            for (int i=0;i<16;i++) {
                float4 vv = vr[i];
                o[4*i] += p*vv.x; o[4*i+1] += p*vv.y;
                o[4*i+2] += p*vv.z; o[4*i+3] += p*vv.w;
            }
        }
        __syncthreads();
    }
    float inv = 1.f / l;
    __half2* d = (__half2*)(Os + (size_t)t*K3);
    #pragma unroll
    for (int i=0;i<16;i++) {
        int c = h*HD + 4*i;
        float vx = o[4*i]*inv, vy = o[4*i+1]*inv, vz = o[4*i+2]*inv, vw = o[4*i+3]*inv;
        __half2 h0,l0,h1,l1;
        split2(vx, vy, h0, l0);
        split2(vz, vw, h1, l1);
        d[c/2] = h0;              d[c/2+1] = h1;
        d[(DMODEL+c)/2] = l0;     d[(DMODEL+c)/2+1] = l1;
        d[(2*DMODEL+c)/2] = h0;   d[(2*DMODEL+c)/2+1] = h1;
    }
}

__global__ void router_kernel(const float* __restrict__ XN, const float* __restrict__ RW) {
    __shared__ float sw[NEXP*DMODEL];
    int tid = threadIdx.x;
    for (int i=tid; i<NEXP*DMODEL/4; i+=256)
        ((float4*)sw)[i] = ((const float4*)RW)[i];
    __syncthreads();
    int warp = tid >> 5, lane = tid & 31;
    int token = blockIdx.x*8 + warp;
    const float* xr = XN + (long long)token*DMODEL;
    float acc[NEXP];
    #pragma unroll
    for (int e=0;e<NEXP;e++) acc[e]=0.f;
    for (int d=lane; d<DMODEL; d+=32) {
        float xv = xr[d];
        #pragma unroll
        for (int e=0;e<NEXP;e++) acc[e] += xv * sw[e*DMODEL + d];
    }
    #pragma unroll
    for (int e=0;e<NEXP;e++)
        #pragma unroll
        for (int off=16; off; off>>=1) acc[e] += __shfl_xor_sync(0xffffffffu, acc[e], off);
    if (lane == 0) {
        float mx = acc[0];
        #pragma unroll
        for (int e=1;e<NEXP;e++) mx = fmaxf(mx, acc[e]);
        float pe[NEXP], sum = 0.f;
        #pragma unroll
        for (int e=0;e<NEXP;e++) { pe[e] = expf(acc[e]-mx); sum += pe[e]; }
        float inv = 1.f/sum;
        #pragma unroll
        for (int e=0;e<NEXP;e++) { pe[e] *= inv; g_probs_all[token*NEXP+e] = pe[e]; }
        int e1 = 0; float p1 = pe[0];
        #pragma unroll
        for (int e=1;e<NEXP;e++) if (pe[e] > p1) { p1 = pe[e]; e1 = e; }
        int e2 = -1; float p2 = -1.f;
        #pragma unroll
        for (int e=0;e<NEXP;e++) if (e != e1 && pe[e] > p2) { p2 = pe[e]; e2 = e; }
        float rn = 1.f/(p1+p2);
        g_topk_e[token*2]   = e1;  g_topk_e[token*2+1] = e2;
        g_topk_p[token*2]   = p1*rn; g_topk_p[token*2+1] = p2*rn;
        atomicAdd(&g_cnt[e1], 1);
        atomicAdd(&g_cnt[e2], 1);
    }
}

__global__ void psum_kernel() {
    int e = blockIdx.x;
    int tid = threadIdx.x;
    float acc = 0.f;
    for (int t=tid; t<NTOK; t+=256) acc += g_probs_all[t*NEXP + e];
    #pragma unroll
    for (int off=16; off; off>>=1) acc += __shfl_xor_sync(0xffffffffu, acc, off);
    __shared__ float red[8];
    if ((tid & 31) == 0) red[tid>>5] = acc;
    __syncthreads();
    if (tid < 8) {
        float v = red[tid];
        #pragma unroll
        for (int off=4; off; off>>=1) v += __shfl_xor_sync(0xffu, v, off);
        if (tid == 0) g_Psum[e] = v;
    }
}

__global__ void finalize_kernel(float* __restrict__ out, int out_size) {
    if (threadIdx.x == 0 && blockIdx.x == 0) {
        int total = 0;
        for (int e=0; e<NEXP; e++) {
            g_off[e] = total; g_cur[e] = total;
            total += ((g_cnt[e] + 127)/128)*128;
        }
        g_off[NEXP] = total;
        float aux = 0.f;
        for (int e=0; e<NEXP; e++)
            aux += ((float)g_cnt[e] / (float)NSLOT) * (g_Psum[e] / (float)NTOK);
        out[out_size-9] = (float)NEXP * aux;
        for (int e=0; e<NEXP; e++) out[out_size-8+e] = (float)g_cnt[e];
    }
}

__global__ void assign_kernel() {
    int token = blockIdx.x*256 + threadIdx.x;
    if (token >= NTOK) return;
    #pragma unroll
    for (int kk=0; kk<TOPK; kk++) {
        int e = g_topk_e[token*2+kk];
        int pos = atomicAdd(&g_cur[e], 1);
        g_perm[pos] = token;
        g_prob[pos] = g_topk_p[token*2+kk];
        g_posOf[token*2+kk] = pos;
    }
}

__global__ void combine_kernel(float* __restrict__ out) {
    int t = blockIdx.x;
    int tid = threadIdx.x;
    int p1i = g_posOf[t*2], p2i = g_posOf[t*2+1];
    float p1 = g_prob[p1i], p2 = g_prob[p2i];
    float4 a  = ((const float4*)(g_x1 + (long long)t*DMODEL))[tid];
    float4 y1 = ((const float4*)(g_Y  + (long long)p1i*DMODEL))[tid];
    float4 y2 = ((const float4*)(g_Y  + (long long)p2i*DMODEL))[tid];
    ((float4*)(out + (long long)t*DMODEL))[tid] = make_float4(
        a.x + p1*y1.x + p2*y2.x, a.y + p1*y1.y + p2*y2.y,
        a.z + p1*y1.z + p2*y2.z, a.w + p1*y1.w + p2*y2.w);
}

extern "C" void kernel_launch(void* const* d_in, const int* in_sizes, int n_in,
                              void* d_out, int out_size) {
    const float* x        = (const float*)d_in[0];
    const float* wq       = (const float*)d_in[1];
    const float* wk       = (const float*)d_in[2];
    const float* wv       = (const float*)d_in[3];
    const float* wo       = (const float*)d_in[4];
    const float* attn_nw  = (const float*)d_in[5];
    const float* ffn_nw   = (const float*)d_in[6];
    const float* router_w = (const float*)d_in[7];
    const float* Wg       = (const float*)d_in[8];
    const float* Wu       = (const float*)d_in[9];
    const float* Wd       = (const float*)d_in[10];
    float* out = (float*)d_out;

    float *p_xn,*p_qkv,*p_x1,*p_Y;
    __half *p_xns,*p_xnt,*p_attns,*p_Wqkvs,*p_Wos,*p_Hh,*p_Wgt,*p_Wut,*p_Wdt;
    int *p_perm, *p_off;
    cudaGetSymbolAddress((void**)&p_xn,   g_xn);
    cudaGetSymbolAddress((void**)&p_xns,  g_xns);
    cudaGetSymbolAddress((void**)&p_xnt,  g_xnt);
    cudaGetSymbolAddress((void**)&p_qkv,  g_qkv);
    cudaGetSymbolAddress((void**)&p_attns,g_attns);
    cudaGetSymbolAddress((void**)&p_x1,   g_x1);
    cudaGetSymbolAddress((void**)&p_Hh,   g_Hh);
    cudaGetSymbolAddress((void**)&p_Y,    g_Y);
    cudaGetSymbolAddress((void**)&p_Wqkvs,g_Wqkvs);
    cudaGetSymbolAddress((void**)&p_Wos,  g_Wos);
    cudaGetSymbolAddress((void**)&p_Wgt,  g_Wgt);
    cudaGetSymbolAddress((void**)&p_Wut,  g_Wut);
    cudaGetSymbolAddress((void**)&p_Wdt,  g_Wdt);
    cudaGetSymbolAddress((void**)&p_perm, g_perm);
    cudaGetSymbolAddress((void**)&p_off,  g_off);

    cudaFuncSetAttribute(mgemm_kernel, cudaFuncAttributeMaxDynamicSharedMemorySize, MG_SMEM);
    cudaFuncSetAttribute(gugemm_kernel, cudaFuncAttributeMaxDynamicSharedMemorySize, MG_SMEM);

    // attn_kernel stays at launch index 3 (ncu profiles idx 3)
    rmsnorm_kernel<<<NTOK, 256>>>(x, attn_nw, nullptr, nullptr, p_xns);            // 0
    cvtsplit3_kernel<<<(NWQ+2*NWK+255)/256, 256>>>(
        (const float4*)wq, (const float4*)wk, (const float4*)wv, p_Wqkvs);         // 1
    mgemm_kernel<<<dim3(QKVN/128, NTOK/128), 256, MG_SMEM>>>(
        p_xns, p_Wqkvs, p_qkv, nullptr, QKVN, K3, nullptr, nullptr, 0, 3);         // 2 (qkv + fused rope)
    attn_kernel<<<dim3(SEQ/64, NHEADS, BATCH), 64>>>(p_qkv, p_attns);              // 3 <- profiled

    init_kernel<<<(NSLOT_PAD+255)/256, 256>>>();

    cvtsplit_kernel<<<(DMODEL*DMODEL/4+255)/256, 256>>>((const float4*)wo, p_Wos, DMODEL, DMODEL*DMODEL/4);

    mgemm_kernel<<<dim3(DMODEL/128, NTOK/128), 256, MG_SMEM>>>(
        p_attns, p_Wos, p_x1, x, DMODEL, K3, nullptr, nullptr, 0, 2);

    rmsnorm_kernel<<<NTOK, 256>>>(p_x1, ffn_nw, p_xn, p_xnt, nullptr);

    router_kernel<<<NTOK/8, 256>>>(p_xn, router_w);
    psum_kernel<<<NEXP, 256>>>();
    finalize_kernel<<<1, 32>>>(out, out_size);
    assign_kernel<<<NTOK/256, 256>>>();

    cvth3_kernel<<<(3*NW4+255)/256, 256>>>(
        (const float4*)Wg, (const float4*)Wu, (const float4*)Wd,
        (__half2*)p_Wgt, (__half2*)p_Wut, (__half2*)p_Wdt);

    gugemm_kernel<<<dim3(DFF/64, NSLOT_PAD/128), 256, MG_SMEM>>>(
        p_xnt, p_Wgt, p_Wut, p_Hh, DFF, DMODEL, p_perm, p_off, (long long)DFF*DMODEL);
    mgemm_kernel<<<dim3(DMODEL/128, NSLOT_PAD/128), 256, MG_SMEM>>>(
        p_Hh, p_Wdt, p_Y, nullptr, DMODEL, DFF, nullptr, p_off, (long long)DMODEL*DFF, 0);

    combine_kernel<<<NTOK, 256>>>(out);
}

// round 17
// speedup vs baseline: 1.2634x; 1.0136x over previous
#include <cuda_runtime.h>
#include <cuda_fp16.h>
#include <math.h>
#include <stdint.h>

#define BATCH 2
#define SEQ 2048
#define NTOK (BATCH*SEQ)
#define DMODEL 1024
#define DFF 2048
#define NHEADS 16
#define NKVHEADS 4
#define HD 64
#define KVDIM (NKVHEADS*HD)
#define QKVN (DMODEL+2*KVDIM)   // 1536
#define K3 (3*DMODEL)           // 3072 split-K
#define NEXP 8
#define TOPK 2
#define NSLOT (NTOK*TOPK)
#define NSLOT_PAD 9216

__device__ float  g_xn[NTOK*DMODEL];
__device__ __half g_xns[NTOK*K3];
__device__ __half g_xnt[NTOK*DMODEL];
__device__ float  g_qkv[NTOK*QKVN];
__device__ __half g_attns[NTOK*K3];
__device__ float  g_x1[NTOK*DMODEL];
__device__ __half g_Hh[NSLOT_PAD*DFF];
__device__ float  g_Y[NSLOT_PAD*DMODEL];
__device__ __half g_Wqkvs[QKVN*K3];
__device__ __half g_Wos[DMODEL*K3];
__device__ __half g_Wgt[NEXP*DFF*DMODEL];
__device__ __half g_Wut[NEXP*DFF*DMODEL];
__device__ __half g_Wdt[NEXP*DMODEL*DFF];
__device__ int    g_perm[NSLOT_PAD];
__device__ float  g_prob[NSLOT_PAD];
__device__ int    g_posOf[NTOK*TOPK];
__device__ int    g_topk_e[NTOK*TOPK];
__device__ float  g_topk_p[NTOK*TOPK];
__device__ float  g_probs_all[NTOK*NEXP];
__device__ int    g_cnt[NEXP];
__device__ int    g_off[NEXP+1];
__device__ int    g_cur[NEXP];
__device__ float  g_Psum[NEXP];

__device__ __forceinline__ void cp16(uint32_t dst, const void* src, uint32_t sz) {
    asm volatile("cp.async.cg.shared.global [%0], [%1], 16, %2;" :: "r"(dst), "l"(src), "r"(sz) : "memory");
}
__device__ __forceinline__ uint32_t smem_u32(const void* p) {
    uint32_t a;
    asm("{ .reg .u64 t; cvta.to.shared.u64 t, %1; cvt.u32.u64 %0, t; }" : "=r"(a) : "l"(p));
    return a;
}
__device__ __forceinline__ void mma16h(float* c, uint32_t a0, uint32_t a1, uint32_t a2,
                                       uint32_t a3, uint32_t b0, uint32_t b1) {
    asm volatile("mma.sync.aligned.m16n8k16.row.col.f32.f16.f16.f32 "
        "{%0,%1,%2,%3}, {%4,%5,%6,%7}, {%8,%9}, {%0,%1,%2,%3};"
        : "+f"(c[0]), "+f"(c[1]), "+f"(c[2]), "+f"(c[3])
        : "r"(a0), "r"(a1), "r"(a2), "r"(a3), "r"(b0), "r"(b1));
}
__device__ __forceinline__ float silu(float g) { return g / (1.f + __expf(-g)); }
__device__ __forceinline__ void split2(float x, float y, __half2& h, __half2& l) {
    __half hx = __float2half_rn(x), hy = __float2half_rn(y);
    h = __halves2half2(hx, hy);
    l = __floats2half2_rn(x - __half2float(hx), y - __half2float(hy));
}

__global__ void init_kernel() {
    int i = blockIdx.x*256 + threadIdx.x;
    if (i < NSLOT_PAD) g_perm[i] = -1;
    if (i < NEXP) { g_cnt[i] = 0; g_Psum[i] = 0.f; }
}

#define NW4 (NEXP*DFF*DMODEL/4)
__global__ void cvth3_kernel(const float4* __restrict__ s0, const float4* __restrict__ s1,
                             const float4* __restrict__ s2, __half2* __restrict__ d0,
                             __half2* __restrict__ d1, __half2* __restrict__ d2) {
    int i = blockIdx.x*256 + threadIdx.x;
    const float4* s; __half2* d; int k;
    if (i < NW4)            { s = s0; d = d0; k = i; }
    else if (i < 2*NW4)     { s = s1; d = d1; k = i - NW4; }
    else if (i < 3*NW4)     { s = s2; d = d2; k = i - 2*NW4; }
    else return;
    float4 v = s[k];
    d[2*k]   = __floats2half2_rn(v.x, v.y);
    d[2*k+1] = __floats2half2_rn(v.z, v.w);
}

__device__ __forceinline__ void cvtsplit_one(const float4* src, __half* dst, int K, int i) {
    int kq = K >> 2;
    int n = i / kq, c = (i - n*kq) * 4;
    float4 v = src[i];
    __half2 h0, l0, h1, l1;
    split2(v.x, v.y, h0, l0);
    split2(v.z, v.w, h1, l1);
    __half2* d = (__half2*)(dst + (size_t)n*3*K);
    d[c/2] = h0;         d[c/2+1] = h1;
    d[(K+c)/2] = h0;     d[(K+c)/2+1] = h1;
    d[(2*K+c)/2] = l0;   d[(2*K+c)/2+1] = l1;
}

__global__ void cvtsplit_kernel(const float4* __restrict__ src, __half* __restrict__ dst,
                                int K, int n4) {
    int i = blockIdx.x*256 + threadIdx.x;
    if (i < n4) cvtsplit_one(src, dst, K, i);
}

#define NWQ (DMODEL*DMODEL/4)
#define NWK (KVDIM*DMODEL/4)
__global__ void cvtsplit3_kernel(const float4* __restrict__ wq, const float4* __restrict__ wk,
                                 const float4* __restrict__ wv, __half* __restrict__ dst) {
    int i = blockIdx.x*256 + threadIdx.x;
    if (i < NWQ) {
        cvtsplit_one(wq, dst, DMODEL, i);
    } else if (i < NWQ + NWK) {
        cvtsplit_one(wk, dst + (size_t)DMODEL*K3, DMODEL, i - NWQ);
    } else if (i < NWQ + 2*NWK) {
        cvtsplit_one(wv, dst + (size_t)(DMODEL+KVDIM)*K3, DMODEL, i - NWQ - NWK);
    }
}

__global__ void rmsnorm_kernel(const float* __restrict__ X, const float* __restrict__ W,
                               float* __restrict__ Y, __half* __restrict__ Yt,
                               __half* __restrict__ Ys) {
    int t = blockIdx.x;
    int tid = threadIdx.x;
    float4 xv = ((const float4*)(X + (long long)t*DMODEL))[tid];
    float ss = xv.x*xv.x + xv.y*xv.y + xv.z*xv.z + xv.w*xv.w;
    #pragma unroll
    for (int off=16; off; off>>=1) ss += __shfl_xor_sync(0xffffffffu, ss, off);
    __shared__ float red[8];
    if ((tid & 31) == 0) red[tid>>5] = ss;
    __syncthreads();
    if (tid < 8) {
        float v = red[tid];
        #pragma unroll
        for (int off=4; off; off>>=1) v += __shfl_xor_sync(0xffu, v, off);
        if (tid == 0) red[0] = v;
    }
    __syncthreads();
    float r = rsqrtf(red[0]/(float)DMODEL + 1e-6f);
    float4 wv = ((const float4*)W)[tid];
    float4 o = make_float4(xv.x*r*wv.x, xv.y*r*wv.y, xv.z*r*wv.z, xv.w*r*wv.w);
    if (Y) ((float4*)(Y + (long long)t*DMODEL))[tid] = o;
    if (Yt) {
        __half2* yh = (__half2*)(Yt + (long long)t*DMODEL);
        yh[2*tid]   = __floats2half2_rn(o.x, o.y);
        yh[2*tid+1] = __floats2half2_rn(o.z, o.w);
    }
    if (Ys) {
        int c = 4*tid;
        __half2 h0,l0,h1,l1;
        split2(o.x, o.y, h0, l0);
        split2(o.z, o.w, h1, l1);
        __half2* d = (__half2*)(Ys + (size_t)t*K3);
        d[c/2] = h0;              d[c/2+1] = h1;
        d[(DMODEL+c)/2] = l0;     d[(DMODEL+c)/2+1] = l1;
        d[(2*DMODEL+c)/2] = h0;   d[(2*DMODEL+c)/2+1] = h1;
    }
}

__device__ __forceinline__ void rope_pair(int row, int col, float& c0, float& c1) {
    int s = row & (SEQ-1);
    int elem = col & 63;
    float f = (float)(elem & 31);
    float freq = powf(10000.f, -f/32.f);
    float ang = (float)s * freq;
    float cc = cosf(ang), sn = sinf(ang);
    float x1 = c0, x2 = c1;
    c0 = x1*cc - x2*sn;
    c1 = x1*sn + x2*cc;
}

// fp16 mma GEMM: acc[M,N] = A[M,K]@B[N,K]^T (fp32 accum), 128x128x64, 3-stage, m16n8k16.
// modes: 0 Cf=acc; 2 Cf=acc+Gf (residual); 3 Cf=rope(acc) (qkv epilogue)
#define HROW 72
#define HSTG_B (128*144)
#define MG_STAGES 3
#define MG_SMEM (MG_STAGES*2*HSTG_B)
__global__ void __launch_bounds__(256,2) mgemm_kernel(
    const __half* __restrict__ A, const __half* __restrict__ B,
    float* __restrict__ Cf, const float* __restrict__ Gf,
    int N, int K, const int* __restrict__ perm, const int* __restrict__ off,
    long long strideB, int mode)
{
    extern __shared__ char smc[];
    int row0 = blockIdx.y * 128;
    int col0 = blockIdx.x * 128;
    if (off) {
        if (row0 >= off[NEXP]) return;
        int e = 0;
        #pragma unroll
        for (int i=1; i<NEXP; i++) if (row0 >= off[i]) e = i;
        B += (long long)e * strideB;
    }
    int tid = threadIdx.x, wid = tid >> 5, lane = tid & 31;
    int r = lane >> 2, cq = lane & 3;
    int wm = (wid & 3) * 32, wn = (wid >> 2) * 64;
    uint32_t sbase = smem_u32(smc);

    int j = tid & 7, rg = tid >> 3;
    const char* gA[4]; uint32_t szA[4]; const char* gB[4]; uint32_t sOf[4];
    #pragma unroll
    for (int i=0;i<4;i++) {
        int rr = rg + i*32;
        sOf[i] = (uint32_t)(rr*144 + j*16);
        int ar = row0 + rr; uint32_t sz = 16;
        if (perm) { int pr = perm[ar]; if (pr < 0) { ar = 0; sz = 0; } else ar = pr; }
        gA[i] = (const char*)(A + (size_t)ar * K) + j*16;
        szA[i] = sz;
        gB[i] = (const char*)(B + (size_t)(col0 + rr) * K) + j*16;
    }

    float acc[2][8][4];
    #pragma unroll
    for (int mt=0;mt<2;mt++)
        #pragma unroll
        for (int nt=0;nt<8;nt++)
            #pragma unroll
            for (int q=0;q<4;q++) acc[mt][nt][q] = 0.f;

    int NC = K >> 6;

    #pragma unroll
    for (int pre=0; pre<2; pre++) {
        uint32_t st = sbase + (uint32_t)(pre * 2*HSTG_B);
        size_t ko = (size_t)pre * 128;
        #pragma unroll
        for (int i=0;i<4;i++) cp16(st + sOf[i], gA[i] + ko, szA[i]);
        #pragma unroll
        for (int i=0;i<4;i++) cp16(st + HSTG_B + sOf[i], gB[i] + ko, 16);
        asm volatile("cp.async.commit_group;" ::: "memory");
    }

    #pragma unroll 1
    for (int c = 0; c < NC; ++c) {
        if (c + 2 < NC) {
            uint32_t st = sbase + (uint32_t)(((c+2)%MG_STAGES) * 2*HSTG_B);
            size_t ko = (size_t)(c+2) * 128;
            #pragma unroll
            for (int i=0;i<4;i++) cp16(st + sOf[i], gA[i] + ko, szA[i]);
            #pragma unroll
            for (int i=0;i<4;i++) cp16(st + HSTG_B + sOf[i], gB[i] + ko, 16);
            asm volatile("cp.async.commit_group;" ::: "memory");
            asm volatile("cp.async.wait_group 2;" ::: "memory");
        } else if (c + 1 < NC) {
            asm volatile("cp.async.wait_group 1;" ::: "memory");
        } else {
            asm volatile("cp.async.wait_group 0;" ::: "memory");
        }
        __syncthreads();
        const __half* sa = (const __half*)(smc + (c%MG_STAGES)*2*HSTG_B);
        const __half* sb = (const __half*)(smc + (c%MG_STAGES)*2*HSTG_B + HSTG_B);
        #pragma unroll
        for (int ks=0; ks<4; ks++) {
            int kk = ks*16 + cq*2;
            uint32_t a[2][4];
            #pragma unroll
            for (int mt=0;mt<2;mt++) {
                int m = wm + mt*16 + r;
                a[mt][0] = *(const uint32_t*)(sa + m*HROW + kk);
                a[mt][1] = *(const uint32_t*)(sa + (m+8)*HROW + kk);
                a[mt][2] = *(const uint32_t*)(sa + m*HROW + kk + 8);
                a[mt][3] = *(const uint32_t*)(sa + (m+8)*HROW + kk + 8);
            }
            #pragma unroll
            for (int nt=0;nt<8;nt++) {
                int n = wn + nt*8 + r;
                uint32_t b0 = *(const uint32_t*)(sb + n*HROW + kk);
                uint32_t b1 = *(const uint32_t*)(sb + n*HROW + kk + 8);
                mma16h(acc[0][nt], a[0][0], a[0][1], a[0][2], a[0][3], b0, b1);
                mma16h(acc[1][nt], a[1][0], a[1][1], a[1][2], a[1][3], b0, b1);
            }
        }
        __syncthreads();
    }

    #pragma unroll
    for (int mt=0;mt<2;mt++) {
        #pragma unroll
        for (int nt=0;nt<8;nt++) {
            int row = row0 + wm + mt*16 + r;
            int col = col0 + wn + nt*8 + cq*2;
            long long i0 = (long long)row*N + col, i1 = (long long)(row+8)*N + col;
            if (mode == 0) {
                *(float2*)(Cf + i0) = make_float2(acc[mt][nt][0], acc[mt][nt][1]);
                *(float2*)(Cf + i1) = make_float2(acc[mt][nt][2], acc[mt][nt][3]);
            } else if (mode == 2) {
                float2 r0 = *(const float2*)(Gf + i0);
                float2 r1 = *(const float2*)(Gf + i1);
                *(float2*)(Cf + i0) = make_float2(acc[mt][nt][0]+r0.x, acc[mt][nt][1]+r0.y);
                *(float2*)(Cf + i1) = make_float2(acc[mt][nt][2]+r1.x, acc[mt][nt][3]+r1.y);
            } else { // mode 3: rope
                float c0 = acc[mt][nt][0], c1 = acc[mt][nt][1];
                float c2 = acc[mt][nt][2], c3 = acc[mt][nt][3];
                if (col < DMODEL + KVDIM) {
                    rope_pair(row,   col, c0, c1);
                    rope_pair(row+8, col, c2, c3);
                }
                *(float2*)(Cf + i0) = make_float2(c0, c1);
                *(float2*)(Cf + i1) = make_float2(c2, c3);
            }
        }
    }
}

// fused g+u grouped GEMM: 128(M)x64(N) tile; writes Hh = silu(g)*u in fp16.
__global__ void __launch_bounds__(256,2) gugemm_kernel(
    const __half* __restrict__ A, const __half* __restrict__ Bg, const __half* __restrict__ Bu,
    __half* __restrict__ Ch, int N, int K,
    const int* __restrict__ perm, const int* __restrict__ off, long long strideB)
{
    extern __shared__ char smc[];
    int row0 = blockIdx.y * 128;
    int col0 = blockIdx.x * 64;
    if (row0 >= off[NEXP]) return;
    {
        int e = 0;
        #pragma unroll
        for (int i=1; i<NEXP; i++) if (row0 >= off[i]) e = i;
        Bg += (long long)e * strideB;
        Bu += (long long)e * strideB;
    }
    int tid = threadIdx.x, wid = tid >> 5, lane = tid & 31;
    int r = lane >> 2, cq = lane & 3;
    int wm = (wid & 3) * 32, wn = (wid >> 2) * 32;
    uint32_t sbase = smem_u32(smc);

    int j = tid & 7, rg = tid >> 3;
    const char* gA[4]; uint32_t szA[4]; const char* gB[4]; uint32_t sOf[4];
    #pragma unroll
    for (int i=0;i<4;i++) {
        int rr = rg + i*32;
        sOf[i] = (uint32_t)(rr*144 + j*16);
        int ar = row0 + rr; uint32_t sz = 16;
        int pr = perm[ar]; if (pr < 0) { ar = 0; sz = 0; } else ar = pr;
        gA[i] = (const char*)(A + (size_t)ar * K) + j*16;
        szA[i] = sz;
        gB[i] = (rr < 64) ? (const char*)(Bg + (size_t)(col0 + rr) * K) + j*16
                          : (const char*)(Bu + (size_t)(col0 + rr - 64) * K) + j*16;
    }

    float accg[2][4][4], accu[2][4][4];
    #pragma unroll
    for (int mt=0;mt<2;mt++)
        #pragma unroll
        for (int nt=0;nt<4;nt++)
            #pragma unroll
            for (int q=0;q<4;q++) { accg[mt][nt][q] = 0.f; accu[mt][nt][q] = 0.f; }

    int NC = K >> 6;

    #pragma unroll
    for (int pre=0; pre<2; pre++) {
        uint32_t st = sbase + (uint32_t)(pre * 2*HSTG_B);
        size_t ko = (size_t)pre * 128;
        #pragma unroll
        for (int i=0;i<4;i++) cp16(st + sOf[i], gA[i] + ko, szA[i]);
        #pragma unroll
        for (int i=0;i<4;i++) cp16(st + HSTG_B + sOf[i], gB[i] + ko, 16);
        asm volatile("cp.async.commit_group;" ::: "memory");
    }

    #pragma unroll 1
    for (int c = 0; c < NC; ++c) {
        if (c + 2 < NC) {
            uint32_t st = sbase + (uint32_t)(((c+2)%MG_STAGES) * 2*HSTG_B);
            size_t ko = (size_t)(c+2) * 128;
            #pragma unroll
            for (int i=0;i<4;i++) cp16(st + sOf[i], gA[i] + ko, szA[i]);
            #pragma unroll
            for (int i=0;i<4;i++) cp16(st + HSTG_B + sOf[i], gB[i] + ko, 16);
            asm volatile("cp.async.commit_group;" ::: "memory");
            asm volatile("cp.async.wait_group 2;" ::: "memory");
        } else if (c + 1 < NC) {
            asm volatile("cp.async.wait_group 1;" ::: "memory");
        } else {
            asm volatile("cp.async.wait_group 0;" ::: "memory");
        }
        __syncthreads();
        const __half* sa = (const __half*)(smc + (c%MG_STAGES)*2*HSTG_B);
        const __half* sb = (const __half*)(smc + (c%MG_STAGES)*2*HSTG_B + HSTG_B);
        #pragma unroll
        for (int ks=0; ks<4; ks++) {
            int kk = ks*16 + cq*2;
            uint32_t a[2][4];
            #pragma unroll
            for (int mt=0;mt<2;mt++) {
                int m = wm + mt*16 + r;
                a[mt][0] = *(const uint32_t*)(sa + m*HROW + kk);
                a[mt][1] = *(const uint32_t*)(sa + (m+8)*HROW + kk);
                a[mt][2] = *(const uint32_t*)(sa + m*HROW + kk + 8);
                a[mt][3] = *(const uint32_t*)(sa + (m+8)*HROW + kk + 8);
            }
            #pragma unroll
            for (int nt=0;nt<4;nt++) {
                int n = wn + nt*8 + r;
                uint32_t bg0 = *(const uint32_t*)(sb + n*HROW + kk);
                uint32_t bg1 = *(const uint32_t*)(sb + n*HROW + kk + 8);
                uint32_t bu0 = *(const uint32_t*)(sb + (n+64)*HROW + kk);
                uint32_t bu1 = *(const uint32_t*)(sb + (n+64)*HROW + kk + 8);
                mma16h(accg[0][nt], a[0][0], a[0][1], a[0][2], a[0][3], bg0, bg1);
                mma16h(accg[1][nt], a[1][0], a[1][1], a[1][2], a[1][3], bg0, bg1);
                mma16h(accu[0][nt], a[0][0], a[0][1], a[0][2], a[0][3], bu0, bu1);
                mma16h(accu[1][nt], a[1][0], a[1][1], a[1][2], a[1][3], bu0, bu1);
            }
        }
        __syncthreads();
    }

    #pragma unroll
    for (int mt=0;mt<2;mt++) {
        #pragma unroll
        for (int nt=0;nt<4;nt++) {
            int row = row0 + wm + mt*16 + r;
            int col = col0 + wn + nt*8 + cq*2;
            *(__half2*)(Ch + (long long)row*N + col) = __floats2half2_rn(
                silu(accg[mt][nt][0])*accu[mt][nt][0], silu(accg[mt][nt][1])*accu[mt][nt][1]);
            *(__half2*)(Ch + (long long)(row+8)*N + col) = __floats2half2_rn(
                silu(accg[mt][nt][2])*accu[mt][nt][2], silu(accg[mt][nt][3])*accu[mt][nt][3]);
        }
    }
}

// flash attention, scalar per-key loop + unroll-2; longest q-tiles launch first (LPT)
__global__ __launch_bounds__(64) void attn_kernel(
    const float* __restrict__ QKV, __half* __restrict__ Os)
{
    __shared__ float Ks[64][64];
    __shared__ float Vs[64][64];
    int tid = threadIdx.x;
    int q0 = (gridDim.x - 1 - blockIdx.x) * 64;
    int h  = blockIdx.y;
    int b  = blockIdx.z;
    int kvh = h >> 2;
    int qi = q0 + tid;
    long long t = (long long)b*SEQ + qi;
    float q[HD], o[HD];
    const float4* qp = (const float4*)(QKV + t*QKVN + h*HD);
    #pragma unroll
    for (int i=0;i<16;i++) {
        float4 f = qp[i];
        q[4*i]=f.x*0.125f; q[4*i+1]=f.y*0.125f; q[4*i+2]=f.z*0.125f; q[4*i+3]=f.w*0.125f;
    }
    #pragma unroll
    for (int d=0; d<HD; d++) o[d] = 0.f;
    float m = -1e30f, l = 0.f;
    int ntiles = q0/64 + 1;
    for (int kt=0; kt<ntiles; kt++) {
        for (int idx=tid; idx<64*16; idx+=64) {
            int rr = idx >> 4, cc = idx & 15;
            long long base = ((long long)(b*SEQ + kt*64 + rr))*QKVN + DMODEL + kvh*HD + cc*4;
            *(float4*)&Ks[rr][cc*4] = *(const float4*)(QKV + base);
            *(float4*)&Vs[rr][cc*4] = *(const float4*)(QKV + base + KVDIM);
        }
        __syncthreads();
        int jend = min(64, qi - kt*64 + 1);
        #pragma unroll 2
        for (int jj=0; jj<jend; jj++) {
            float s0=0.f,s1=0.f,s2=0.f,s3=0.f;
            const float4* kr = (const float4*)&Ks[jj][0];
            #pragma unroll
            for (int i=0;i<16;i++) {
                float4 kv4 = kr[i];
                s0 += q[4*i]*kv4.x; s1 += q[4*i+1]*kv4.y;
                s2 += q[4*i+2]*kv4.z; s3 += q[4*i+3]*kv4.w;
            }
            float s = (s0+s1)+(s2+s3);
            if (s > m) {
                float corr = __expf(m - s);
                l *= corr;
                #pragma unroll
                for (int d=0; d<HD; d++) o[d] *= corr;
                m = s;
            }
            float p = __expf(s - m);
            l += p;
            const float4* vr = (const float4*)&Vs[jj][0];
            #pragma unroll
            for (int i=0;i<16;i++) {
                float4 vv = vr[i];
                o[4*i] += p*vv.x; o[4*i+1] += p*vv.y;
                o[4*i+2] += p*vv.z; o[4*i+3] += p*vv.w;
            }
        }
        __syncthreads();
    }
    float inv = 1.f / l;
    __half2* d = (__half2*)(Os + (size_t)t*K3);
    #pragma unroll
    for (int i=0;i<16;i++) {
        int c = h*HD + 4*i;
        float vx = o[4*i]*inv, vy = o[4*i+1]*inv, vz = o[4*i+2]*inv, vw = o[4*i+3]*inv;
        __half2 h0,l0,h1,l1;
        split2(vx, vy, h0, l0);
        split2(vz, vw, h1, l1);
        d[c/2] = h0;              d[c/2+1] = h1;
        d[(DMODEL+c)/2] = l0;     d[(DMODEL+c)/2+1] = l1;
        d[(2*DMODEL+c)/2] = h0;   d[(2*DMODEL+c)/2+1] = h1;
    }
}

__global__ void router_kernel(const float* __restrict__ XN, const float* __restrict__ RW) {
    __shared__ float sw[NEXP*DMODEL];
    int tid = threadIdx.x;
    for (int i=tid; i<NEXP*DMODEL/4; i+=256)
        ((float4*)sw)[i] = ((const float4*)RW)[i];
    __syncthreads();
    int warp = tid >> 5, lane = tid & 31;
    int token = blockIdx.x*8 + warp;
    const float* xr = XN + (long long)token*DMODEL;
    float acc[NEXP];
    #pragma unroll
    for (int e=0;e<NEXP;e++) acc[e]=0.f;
    for (int d=lane; d<DMODEL; d+=32) {
        float xv = xr[d];
        #pragma unroll
        for (int e=0;e<NEXP;e++) acc[e] += xv * sw[e*DMODEL + d];
    }
    #pragma unroll
    for (int e=0;e<NEXP;e++)
        #pragma unroll
        for (int off=16; off; off>>=1) acc[e] += __shfl_xor_sync(0xffffffffu, acc[e], off);
    if (lane == 0) {
        float mx = acc[0];
        #pragma unroll
        for (int e=1;e<NEXP;e++) mx = fmaxf(mx, acc[e]);
        float pe[NEXP], sum = 0.f;
        #pragma unroll
        for (int e=0;e<NEXP;e++) { pe[e] = expf(acc[e]-mx); sum += pe[e]; }
        float inv = 1.f/sum;
        #pragma unroll
        for (int e=0;e<NEXP;e++) { pe[e] *= inv; g_probs_all[token*NEXP+e] = pe[e]; }
        int e1 = 0; float p1 = pe[0];
        #pragma unroll
        for (int e=1;e<NEXP;e++) if (pe[e] > p1) { p1 = pe[e]; e1 = e; }
        int e2 = -1; float p2 = -1.f;
        #pragma unroll
        for (int e=0;e<NEXP;e++) if (e != e1 && pe[e] > p2) { p2 = pe[e]; e2 = e; }
        float rn = 1.f/(p1+p2);
        g_topk_e[token*2]   = e1;  g_topk_e[token*2+1] = e2;
        g_topk_p[token*2]   = p1*rn; g_topk_p[token*2+1] = p2*rn;
        atomicAdd(&g_cnt[e1], 1);
        atomicAdd(&g_cnt[e2], 1);
    }
}

__global__ void psum_kernel() {
    int e = blockIdx.x;
    int tid = threadIdx.x;
    float acc = 0.f;
    for (int t=tid; t<NTOK; t+=256) acc += g_probs_all[t*NEXP + e];
    #pragma unroll
    for (int off=16; off; off>>=1) acc += __shfl_xor_sync(0xffffffffu, acc, off);
    __shared__ float red[8];
    if ((tid & 31) == 0) red[tid>>5] = acc;
    __syncthreads();
    if (tid < 8) {
        float v = red[tid];
        #pragma unroll
        for (int off=4; off; off>>=1) v += __shfl_xor_sync(0xffu, v, off);
        if (tid == 0) g_Psum[e] = v;
    }
}

__global__ void finalize_kernel(float* __restrict__ out, int out_size) {
    if (threadIdx.x == 0 && blockIdx.x == 0) {
        int total = 0;
        for (int e=0; e<NEXP; e++) {
            g_off[e] = total; g_cur[e] = total;
            total += ((g_cnt[e] + 127)/128)*128;
        }
        g_off[NEXP] = total;
        float aux = 0.f;
        for (int e=0; e<NEXP; e++)
            aux += ((float)g_cnt[e] / (float)NSLOT) * (g_Psum[e] / (float)NTOK);
        out[out_size-9] = (float)NEXP * aux;
        for (int e=0; e<NEXP; e++) out[out_size-8+e] = (float)g_cnt[e];
    }
}

__global__ void assign_kernel() {
    int token = blockIdx.x*256 + threadIdx.x;
    if (token >= NTOK) return;
    #pragma unroll
    for (int kk=0; kk<TOPK; kk++) {
        int e = g_topk_e[token*2+kk];
        int pos = atomicAdd(&g_cur[e], 1);
        g_perm[pos] = token;
        g_prob[pos] = g_topk_p[token*2+kk];
        g_posOf[token*2+kk] = pos;
    }
}

__global__ void combine_kernel(float* __restrict__ out) {
    int t = blockIdx.x;
    int tid = threadIdx.x;
    int p1i = g_posOf[t*2], p2i = g_posOf[t*2+1];
    float p1 = g_prob[p1i], p2 = g_prob[p2i];
    float4 a  = ((const float4*)(g_x1 + (long long)t*DMODEL))[tid];
    float4 y1 = ((const float4*)(g_Y  + (long long)p1i*DMODEL))[tid];
    float4 y2 = ((const float4*)(g_Y  + (long long)p2i*DMODEL))[tid];
    ((float4*)(out + (long long)t*DMODEL))[tid] = make_float4(
        a.x + p1*y1.x + p2*y2.x, a.y + p1*y1.y + p2*y2.y,
        a.z + p1*y1.z + p2*y2.z, a.w + p1*y1.w + p2*y2.w);
}

extern "C" void kernel_launch(void* const* d_in, const int* in_sizes, int n_in,
                              void* d_out, int out_size) {
    const float* x        = (const float*)d_in[0];
    const float* wq       = (const float*)d_in[1];
    const float* wk       = (const float*)d_in[2];
    const float* wv       = (const float*)d_in[3];
    const float* wo       = (const float*)d_in[4];
    const float* attn_nw  = (const float*)d_in[5];
    const float* ffn_nw   = (const float*)d_in[6];
    const float* router_w = (const float*)d_in[7];
    const float* Wg       = (const float*)d_in[8];
    const float* Wu       = (const float*)d_in[9];
    const float* Wd       = (const float*)d_in[10];
    float* out = (float*)d_out;

    float *p_xn,*p_qkv,*p_x1,*p_Y;
    __half *p_xns,*p_xnt,*p_attns,*p_Wqkvs,*p_Wos,*p_Hh,*p_Wgt,*p_Wut,*p_Wdt;
    int *p_perm, *p_off;
    cudaGetSymbolAddress((void**)&p_xn,   g_xn);
    cudaGetSymbolAddress((void**)&p_xns,  g_xns);
    cudaGetSymbolAddress((void**)&p_xnt,  g_xnt);
    cudaGetSymbolAddress((void**)&p_qkv,  g_qkv);
    cudaGetSymbolAddress((void**)&p_attns,g_attns);
    cudaGetSymbolAddress((void**)&p_x1,   g_x1);
    cudaGetSymbolAddress((void**)&p_Hh,   g_Hh);
    cudaGetSymbolAddress((void**)&p_Y,    g_Y);
    cudaGetSymbolAddress((void**)&p_Wqkvs,g_Wqkvs);
    cudaGetSymbolAddress((void**)&p_Wos,  g_Wos);
    cudaGetSymbolAddress((void**)&p_Wgt,  g_Wgt);
    cudaGetSymbolAddress((void**)&p_Wut,  g_Wut);
    cudaGetSymbolAddress((void**)&p_Wdt,  g_Wdt);
    cudaGetSymbolAddress((void**)&p_perm, g_perm);
    cudaGetSymbolAddress((void**)&p_off,  g_off);

    cudaFuncSetAttribute(mgemm_kernel, cudaFuncAttributeMaxDynamicSharedMemorySize, MG_SMEM);
    cudaFuncSetAttribute(gugemm_kernel, cudaFuncAttributeMaxDynamicSharedMemorySize, MG_SMEM);

    // lazily-created side stream + events (host-side objects; first call is the
    // un-captured correctness run, so creation never happens inside capture)
    static cudaStream_t s_side = nullptr;
    static cudaEvent_t ev_fork = nullptr, ev_join = nullptr;
    if (!s_side) {
        cudaStreamCreateWithFlags(&s_side, cudaStreamNonBlocking);
        cudaEventCreateWithFlags(&ev_fork, cudaEventDisableTiming);
        cudaEventCreateWithFlags(&ev_join, cudaEventDisableTiming);
    }

    // ---- fork: input-independent weight conversion runs beside the attention chain
    cudaEventRecord(ev_fork, 0);
    cudaStreamWaitEvent(s_side, ev_fork, 0);
    cvth3_kernel<<<(3*NW4+255)/256, 256, 0, s_side>>>(
        (const float4*)Wg, (const float4*)Wu, (const float4*)Wd,
        (__half2*)p_Wgt, (__half2*)p_Wut, (__half2*)p_Wdt);
    cvtsplit_kernel<<<(DMODEL*DMODEL/4+255)/256, 256, 0, s_side>>>(
        (const float4*)wo, p_Wos, DMODEL, DMODEL*DMODEL/4);
    init_kernel<<<(NSLOT_PAD+255)/256, 256, 0, s_side>>>();
    cudaEventRecord(ev_join, s_side);

    // ---- main chain
    rmsnorm_kernel<<<NTOK, 256>>>(x, attn_nw, nullptr, nullptr, p_xns);
    cvtsplit3_kernel<<<(NWQ+2*NWK+255)/256, 256>>>(
        (const float4*)wq, (const float4*)wk, (const float4*)wv, p_Wqkvs);
    mgemm_kernel<<<dim3(QKVN/128, NTOK/128), 256, MG_SMEM>>>(
        p_xns, p_Wqkvs, p_qkv, nullptr, QKVN, K3, nullptr, nullptr, 0, 3);
    attn_kernel<<<dim3(SEQ/64, NHEADS, BATCH), 64>>>(p_qkv, p_attns);

    // ---- join: Wos/init ready before wo-gemm / assign
    cudaStreamWaitEvent(0, ev_join, 0);

    mgemm_kernel<<<dim3(DMODEL/128, NTOK/128), 256, MG_SMEM>>>(
        p_attns, p_Wos, p_x1, x, DMODEL, K3, nullptr, nullptr, 0, 2);

    rmsnorm_kernel<<<NTOK, 256>>>(p_x1, ffn_nw, p_xn, p_xnt, nullptr);

    router_kernel<<<NTOK/8, 256>>>(p_xn, router_w);
    psum_kernel<<<NEXP, 256>>>();
    finalize_kernel<<<1, 32>>>(out, out_size);
    assign_kernel<<<NTOK/256, 256>>>();

    gugemm_kernel<<<dim3(DFF/64, NSLOT_PAD/128), 256, MG_SMEM>>>(
        p_xnt, p_Wgt, p_Wut, p_Hh, DFF, DMODEL, p_perm, p_off, (long long)DFF*DMODEL);
    mgemm_kernel<<<dim3(DMODEL/128, NSLOT_PAD/128), 256, MG_SMEM>>>(
        p_Hh, p_Wdt, p_Y, nullptr, DMODEL, DFF, nullptr, p_off, (long long)DMODEL*DFF, 0);

    combine_kernel<<<NTOK, 256>>>(out);
}